// round 1
// baseline (speedup 1.0000x reference)
#include <cuda_runtime.h>
#include <math.h>

#define S_LEN   2048
#define BATCH   2
#define NH      16
#define HID     2048
#define QL      1536
#define KVL     512
#define DR      64
#define DN      128
#define DVV     128
#define DQK     192
#define NTOK    (BATCH * S_LEN)     // 4096
#define CKV_W   (KVL + DR)          // 576

// ---------------- scratch (static device globals; no runtime allocation) ----
__device__ float g_qa [NTOK * QL];          // hidden @ q_a_w  (rmsnorm in-place)
__device__ float g_q  [NTOK * NH * DQK];    // q_b output, [tok][h][192], rope in-place
__device__ float g_ckv[NTOK * CKV_W];       // hidden @ kv_a_w
__device__ float g_ckn[NTOK * KVL];         // rmsnorm(compressed_kv)
__device__ float g_kv [NTOK * NH * 256];    // kv_b output, [tok][h][256] (nope|value)
__device__ float g_kr [NTOK * DR];          // rope'd k_rope (shared across heads)
__device__ float g_ao [NTOK * NH * DVV];    // attention output, [tok][h*128+d]

// ---------------- generic fp32 GEMM: C[M,N] = A[M,K] @ B[K,N] ---------------
// 128x128 block tile, BK=16, 256 threads, 8x8 microtile.
// A staged transposed in smem -> inner loop is float4 LDS + FFMA (FMA-bound).
__global__ __launch_bounds__(256) void gemm_kernel(
    const float* __restrict__ A, const float* __restrict__ B,
    float* __restrict__ C, int M, int N, int K)
{
    __shared__ float At[16][132];
    __shared__ float Bs[16][132];
    const int tid = threadIdx.x;
    const int ty = tid >> 4, tx = tid & 15;
    const int row0 = blockIdx.y << 7;
    const int col0 = blockIdx.x << 7;
    const int r0 = ty << 3, c0 = tx << 3;

    float acc[8][8];
    #pragma unroll
    for (int i = 0; i < 8; i++)
        #pragma unroll
        for (int j = 0; j < 8; j++) acc[i][j] = 0.f;

    for (int k0 = 0; k0 < K; k0 += 16) {
        // stage A tile transposed: At[k][m]
        #pragma unroll
        for (int i = 0; i < 2; i++) {
            int f = tid + (i << 8);
            int m = f >> 2;
            int kq = (f & 3) << 2;
            float4 v = *reinterpret_cast<const float4*>(
                &A[(size_t)(row0 + m) * K + k0 + kq]);
            At[kq + 0][m] = v.x; At[kq + 1][m] = v.y;
            At[kq + 2][m] = v.z; At[kq + 3][m] = v.w;
        }
        // stage B tile row-major: Bs[k][c]  (guard ragged N, e.g. N=576)
        #pragma unroll
        for (int i = 0; i < 2; i++) {
            int f = tid + (i << 8);
            int kr = f >> 5;
            int c  = (f & 31) << 2;
            float4 v = make_float4(0.f, 0.f, 0.f, 0.f);
            if (col0 + c < N)   // N is a multiple of 4 -> whole float4 valid
                v = *reinterpret_cast<const float4*>(
                    &B[(size_t)(k0 + kr) * N + col0 + c]);
            *reinterpret_cast<float4*>(&Bs[kr][c]) = v;
        }
        __syncthreads();

        #pragma unroll
        for (int kk = 0; kk < 16; kk++) {
            float4 a0 = *reinterpret_cast<float4*>(&At[kk][r0]);
            float4 a1 = *reinterpret_cast<float4*>(&At[kk][r0 + 4]);
            float4 b0 = *reinterpret_cast<float4*>(&Bs[kk][c0]);
            float4 b1 = *reinterpret_cast<float4*>(&Bs[kk][c0 + 4]);
            float a[8] = {a0.x, a0.y, a0.z, a0.w, a1.x, a1.y, a1.z, a1.w};
            float b[8] = {b0.x, b0.y, b0.z, b0.w, b1.x, b1.y, b1.z, b1.w};
            #pragma unroll
            for (int i = 0; i < 8; i++)
                #pragma unroll
                for (int j = 0; j < 8; j++)
                    acc[i][j] = fmaf(a[i], b[j], acc[i][j]);
        }
        __syncthreads();
    }

    #pragma unroll
    for (int i = 0; i < 8; i++) {
        int r = row0 + r0 + i;
        #pragma unroll
        for (int j = 0; j < 8; j++) {
            int c = col0 + c0 + j;
            if (c < N) C[(size_t)r * N + c] = acc[i][j];
        }
    }
}

// ---------------- RMSNorm: out[row] = w * x * rsqrt(mean(x^2)+eps) ----------
__global__ __launch_bounds__(256) void rmsnorm_kernel(
    const float* __restrict__ in, const float* __restrict__ w,
    float* __restrict__ out, int in_stride, int out_stride, int n)
{
    const int row = blockIdx.x;
    const float* x = in + (size_t)row * in_stride;
    float ss = 0.f;
    for (int j = threadIdx.x; j < n; j += 256) { float v = x[j]; ss += v * v; }
    __shared__ float red[8];
    #pragma unroll
    for (int off = 16; off; off >>= 1) ss += __shfl_xor_sync(~0u, ss, off);
    if ((threadIdx.x & 31) == 0) red[threadIdx.x >> 5] = ss;
    __syncthreads();
    if (threadIdx.x == 0) {
        float t = 0.f;
        #pragma unroll
        for (int i = 0; i < 8; i++) t += red[i];
        red[0] = rsqrtf(t / n + 1e-6f);
    }
    __syncthreads();
    const float r = red[0];
    float* y = out + (size_t)row * out_stride;
    for (int j = threadIdx.x; j < n; j += 256) y[j] = w[j] * x[j] * r;
}

// ---------------- RoPE (interleaved, cv = cos[s, 0::2]) ---------------------
__global__ void rope_q_kernel(float* __restrict__ q,
                              const float* __restrict__ cosb,
                              const float* __restrict__ sinb)
{
    const int t = blockIdx.x;
    const int h = threadIdx.x >> 5;
    const int i = threadIdx.x & 31;
    const int s = t & (S_LEN - 1);
    const float cv = cosb[s * DR + 2 * i];
    const float sv = sinb[s * DR + 2 * i];
    float* p = q + (size_t)t * NH * DQK + h * DQK + DN + 2 * i;
    const float xr = p[0], xi = p[1];
    p[0] = xr * cv - xi * sv;
    p[1] = xr * sv + xi * cv;
}

__global__ void rope_k_kernel(const float* __restrict__ ckv,
                              const float* __restrict__ cosb,
                              const float* __restrict__ sinb,
                              float* __restrict__ kr)
{
    const int t = blockIdx.x;
    const int i = threadIdx.x;            // 0..31 (pairs)
    const int s = t & (S_LEN - 1);
    const float cv = cosb[s * DR + 2 * i];
    const float sv = sinb[s * DR + 2 * i];
    const float xr = ckv[(size_t)t * CKV_W + KVL + 2 * i];
    const float xi = ckv[(size_t)t * CKV_W + KVL + 2 * i + 1];
    kr[t * DR + 2 * i]     = xr * cv - xi * sv;
    kr[t * DR + 2 * i + 1] = xr * sv + xi * cv;
}

// ---------------- Flash attention (fp32, online softmax) --------------------
// grid (S/64, B*H), 256 threads. BM=BN=64. Q/K stored transposed in smem.
#define ATTN_SMEM_FLOATS (192*68 + 192*68 + 64*132 + 64*68)
#define ATTN_SMEM_BYTES  (ATTN_SMEM_FLOATS * 4)

__global__ __launch_bounds__(256) void attn_kernel(
    const float* __restrict__ q, const float* __restrict__ kv,
    const float* __restrict__ kr, float* __restrict__ ao)
{
    extern __shared__ float sm[];
    float* smQ = sm;                         // [192][68] transposed
    float* smK = smQ + 192 * 68;             // [192][68] transposed
    float* smV = smK + 192 * 68;             // [64][132] row-major
    float* smP = smV + 64 * 132;             // [64][68]  transposed P

    const int tid = threadIdx.x;
    const int ty = tid >> 4, tx = tid & 15;
    const int bh = blockIdx.y;
    const int b = bh >> 4, h = bh & 15;
    const int q0 = blockIdx.x << 6;
    const size_t tokbase = (size_t)b * S_LEN;
    const float scale = 1.0f / sqrtf((float)DQK);

    // load Q tile, transposed (rope already applied in-place)
    for (int idx = tid; idx < 64 * DQK; idx += 256) {
        int r = idx / DQK, d = idx - r * DQK;
        smQ[d * 68 + r] = q[(tokbase + q0 + r) * (NH * DQK) + h * DQK + d];
    }

    float m[4], l[4], o[4][8];
    #pragma unroll
    for (int i = 0; i < 4; i++) {
        m[i] = -3.0e38f; l[i] = 0.f;
        #pragma unroll
        for (int j = 0; j < 8; j++) o[i][j] = 0.f;
    }

    for (int kb = 0; kb < S_LEN; kb += 64) {
        // stage K tile (nope from kv, rope from kr), transposed
        for (int idx = tid; idx < 64 * DQK; idx += 256) {
            int r = idx / DQK, d = idx - r * DQK;
            float v;
            if (d < DN) v = kv[(tokbase + kb + r) * (NH * 256) + h * 256 + d];
            else        v = kr[(tokbase + kb + r) * DR + (d - DN)];
            smK[d * 68 + r] = v;
        }
        // stage V tile row-major
        for (int idx = tid; idx < 64 * DVV; idx += 256) {
            int r = idx >> 7, d = idx & 127;
            smV[r * 132 + d] = kv[(tokbase + kb + r) * (NH * 256) + h * 256 + DN + d];
        }
        __syncthreads();

        // S = Q @ K^T  (4x4 microtile)
        float s4[4][4];
        #pragma unroll
        for (int i = 0; i < 4; i++)
            #pragma unroll
            for (int j = 0; j < 4; j++) s4[i][j] = 0.f;

        #pragma unroll 4
        for (int kk = 0; kk < DQK; kk++) {
            float4 qa = *reinterpret_cast<float4*>(&smQ[kk * 68 + (ty << 2)]);
            float4 ka = *reinterpret_cast<float4*>(&smK[kk * 68 + (tx << 2)]);
            float a[4] = {qa.x, qa.y, qa.z, qa.w};
            float c[4] = {ka.x, ka.y, ka.z, ka.w};
            #pragma unroll
            for (int i = 0; i < 4; i++)
                #pragma unroll
                for (int j = 0; j < 4; j++)
                    s4[i][j] = fmaf(a[i], c[j], s4[i][j]);
        }

        // online softmax (row spans tx lanes; width-16 shuffles)
        #pragma unroll
        for (int i = 0; i < 4; i++) {
            #pragma unroll
            for (int j = 0; j < 4; j++) s4[i][j] *= scale;
            float mx = fmaxf(fmaxf(s4[i][0], s4[i][1]), fmaxf(s4[i][2], s4[i][3]));
            #pragma unroll
            for (int off = 1; off < 16; off <<= 1)
                mx = fmaxf(mx, __shfl_xor_sync(~0u, mx, off, 16));
            float nm = fmaxf(m[i], mx);
            float alpha = __expf(m[i] - nm);
            float ls = 0.f;
            #pragma unroll
            for (int j = 0; j < 4; j++) {
                float p = __expf(s4[i][j] - nm);
                s4[i][j] = p; ls += p;
            }
            #pragma unroll
            for (int off = 1; off < 16; off <<= 1)
                ls += __shfl_xor_sync(~0u, ls, off, 16);
            l[i] = l[i] * alpha + ls;
            m[i] = nm;
            #pragma unroll
            for (int j = 0; j < 8; j++) o[i][j] *= alpha;
            #pragma unroll
            for (int j = 0; j < 4; j++)
                smP[((tx << 2) + j) * 68 + (ty << 2) + i] = s4[i][j];
        }
        __syncthreads();

        // O += P @ V  (4x8 microtile)
        #pragma unroll 4
        for (int kk = 0; kk < 64; kk++) {
            float4 pa = *reinterpret_cast<float4*>(&smP[kk * 68 + (ty << 2)]);
            float4 v0 = *reinterpret_cast<float4*>(&smV[kk * 132 + (tx << 3)]);
            float4 v1 = *reinterpret_cast<float4*>(&smV[kk * 132 + (tx << 3) + 4]);
            float p[4] = {pa.x, pa.y, pa.z, pa.w};
            float v[8] = {v0.x, v0.y, v0.z, v0.w, v1.x, v1.y, v1.z, v1.w};
            #pragma unroll
            for (int i = 0; i < 4; i++)
                #pragma unroll
                for (int j = 0; j < 8; j++)
                    o[i][j] = fmaf(p[i], v[j], o[i][j]);
        }
        __syncthreads();
    }

    // epilogue: normalize and write [tok][h*128 + d]
    #pragma unroll
    for (int i = 0; i < 4; i++) {
        float inv = 1.0f / l[i];
        size_t row = (tokbase + q0 + (ty << 2) + i) * (size_t)(NH * DVV) + h * DVV;
        #pragma unroll
        for (int j = 0; j < 8; j++)
            ao[row + (tx << 3) + j] = o[i][j] * inv;
    }
}

// ---------------- launch ----------------------------------------------------
extern "C" void kernel_launch(void* const* d_in, const int* in_sizes, int n_in,
                              void* d_out, int out_size)
{
    const float* hidden  = (const float*)d_in[0];
    const float* cosb    = (const float*)d_in[1];
    const float* sinb    = (const float*)d_in[2];
    const float* q_a_w   = (const float*)d_in[3];
    const float* q_a_ln  = (const float*)d_in[4];
    const float* q_b_w   = (const float*)d_in[5];
    const float* kv_a_w  = (const float*)d_in[6];
    const float* kv_a_ln = (const float*)d_in[7];
    const float* kv_b_w  = (const float*)d_in[8];
    const float* o_w     = (const float*)d_in[9];
    float* out = (float*)d_out;

    float *qa, *qq, *ckv, *ckn, *kvf, *kr, *ao;
    cudaGetSymbolAddress((void**)&qa,  g_qa);
    cudaGetSymbolAddress((void**)&qq,  g_q);
    cudaGetSymbolAddress((void**)&ckv, g_ckv);
    cudaGetSymbolAddress((void**)&ckn, g_ckn);
    cudaGetSymbolAddress((void**)&kvf, g_kv);
    cudaGetSymbolAddress((void**)&kr,  g_kr);
    cudaGetSymbolAddress((void**)&ao,  g_ao);

    cudaFuncSetAttribute(attn_kernel,
        cudaFuncAttributeMaxDynamicSharedMemorySize, ATTN_SMEM_BYTES);

    // 1) q_a = hidden @ q_a_w          [4096,2048]@[2048,1536]
    gemm_kernel<<<dim3(QL / 128, NTOK / 128), 256>>>(hidden, q_a_w, qa, NTOK, QL, HID);
    // 2) ckv = hidden @ kv_a_w         [4096,2048]@[2048,576]
    gemm_kernel<<<dim3((CKV_W + 127) / 128, NTOK / 128), 256>>>(hidden, kv_a_w, ckv, NTOK, CKV_W, HID);
    // 3) rmsnorm q_a (in-place)
    rmsnorm_kernel<<<NTOK, 256>>>(qa, q_a_ln, qa, QL, QL, QL);
    // 4) rmsnorm compressed_kv -> ckn
    rmsnorm_kernel<<<NTOK, 256>>>(ckv, kv_a_ln, ckn, CKV_W, KVL, KVL);
    // 5) q = qa_n @ q_b_w              [4096,1536]@[1536,3072]
    gemm_kernel<<<dim3((NH * DQK) / 128, NTOK / 128), 256>>>(qa, q_b_w, qq, NTOK, NH * DQK, QL);
    // 6) kv = ckn @ kv_b_w             [4096,512]@[512,4096]
    gemm_kernel<<<dim3((NH * 256) / 128, NTOK / 128), 256>>>(ckn, kv_b_w, kvf, NTOK, NH * 256, KVL);
    // 7) rope on q (in-place, per head)
    rope_q_kernel<<<NTOK, NH * 32>>>(qq, cosb, sinb);
    // 8) rope on shared k_rope -> kr
    rope_k_kernel<<<NTOK, 32>>>(ckv, cosb, sinb, kr);
    // 9) flash attention -> ao
    attn_kernel<<<dim3(S_LEN / 64, BATCH * NH), 256, ATTN_SMEM_BYTES>>>(qq, kvf, kr, ao);
    // 10) out = ao @ o_w               [4096,2048]@[2048,2048]
    gemm_kernel<<<dim3(HID / 128, NTOK / 128), 256>>>(ao, o_w, out, NTOK, HID, HID);
}

// round 3
// speedup vs baseline: 3.8281x; 3.8281x over previous
#include <cuda_runtime.h>
#include <math.h>
#include <stdint.h>

#define S_LEN   2048
#define BATCH   2
#define NH      16
#define HID     2048
#define QL      1536
#define KVL     512
#define DR      64
#define DN      128
#define DVV     128
#define DQK     192
#define NTOK    (BATCH * S_LEN)     // 4096
#define CKV_W   (KVL + DR)          // 576

// ---------------- scratch (static device globals) ---------------------------
__device__ float g_qa [NTOK * QL];
__device__ float g_q  [NTOK * NH * DQK];
__device__ float g_ckv[NTOK * CKV_W];
__device__ float g_ckn[NTOK * KVL];
__device__ float g_kv [NTOK * NH * 256];
__device__ float g_kr [NTOK * DR];
__device__ float g_ao [NTOK * NH * DVV];

// ---------------- tf32 helpers ----------------------------------------------
__device__ __forceinline__ float to_tf32(float x) {
    uint32_t u;
    asm("cvt.rna.tf32.f32 %0, %1;" : "=r"(u) : "f"(x));
    return __uint_as_float(u);
}
__device__ __forceinline__ uint32_t fb(float x) { return __float_as_uint(x); }

__device__ __forceinline__ void mma_tf32(float (&c)[4],
    uint32_t a0, uint32_t a1, uint32_t a2, uint32_t a3,
    uint32_t b0, uint32_t b1)
{
    asm volatile(
        "mma.sync.aligned.m16n8k8.row.col.f32.tf32.tf32.f32 "
        "{%0,%1,%2,%3},{%4,%5,%6,%7},{%8,%9},{%0,%1,%2,%3};"
        : "+f"(c[0]), "+f"(c[1]), "+f"(c[2]), "+f"(c[3])
        : "r"(a0), "r"(a1), "r"(a2), "r"(a3), "r"(b0), "r"(b1));
}

// ---------------- TF32 GEMM: C[M,N] = A[M,K] @ B[K,N] -----------------------
// 128x128 block, BK=16, 256 threads, warp grid 2(M)x4(N), warp tile 64x32.
#define GA_ST 20    // A smem stride (pad: 20 % 32 == 20, A-frag conflict-free)
#define GB_ST 136   // B smem stride (136 % 32 == 8, B-frag conflict-free)

__global__ __launch_bounds__(256) void gemm_tf32(
    const float* __restrict__ A, const float* __restrict__ B,
    float* __restrict__ C, int M, int N, int K)
{
    __shared__ float As[128 * GA_ST];
    __shared__ float Bs[16 * GB_ST];
    const int tid = threadIdx.x;
    const int wid = tid >> 5, lane = tid & 31;
    const int wm = wid >> 2, wn = wid & 3;
    const int row0 = blockIdx.y << 7;
    const int col0 = blockIdx.x << 7;
    const int tg = lane & 3, gp = lane >> 2;

    float acc[4][4][4];
    #pragma unroll
    for (int mt = 0; mt < 4; mt++)
        #pragma unroll
        for (int nt = 0; nt < 4; nt++)
            #pragma unroll
            for (int r = 0; r < 4; r++) acc[mt][nt][r] = 0.f;

    for (int k0 = 0; k0 < K; k0 += 16) {
        // stage A [128][16] (tf32-rounded)
        #pragma unroll
        for (int i = 0; i < 2; i++) {
            int f = tid + (i << 8);
            int m = f >> 2, kq = (f & 3) << 2;
            float4 v = *reinterpret_cast<const float4*>(
                &A[(size_t)(row0 + m) * K + k0 + kq]);
            v.x = to_tf32(v.x); v.y = to_tf32(v.y);
            v.z = to_tf32(v.z); v.w = to_tf32(v.w);
            *reinterpret_cast<float4*>(&As[m * GA_ST + kq]) = v;
        }
        // stage B [16][128]
        #pragma unroll
        for (int i = 0; i < 2; i++) {
            int f = tid + (i << 8);
            int kr = f >> 5, c = (f & 31) << 2;
            float4 v = make_float4(0.f, 0.f, 0.f, 0.f);
            if (col0 + c < N)
                v = *reinterpret_cast<const float4*>(
                    &B[(size_t)(k0 + kr) * N + col0 + c]);
            v.x = to_tf32(v.x); v.y = to_tf32(v.y);
            v.z = to_tf32(v.z); v.w = to_tf32(v.w);
            *reinterpret_cast<float4*>(&Bs[kr * GB_ST + c]) = v;
        }
        __syncthreads();

        #pragma unroll
        for (int ks = 0; ks < 2; ks++) {
            const int kk = ks << 3;
            uint32_t a[4][4];
            #pragma unroll
            for (int mt = 0; mt < 4; mt++) {
                int ra = (wm << 6) + (mt << 4) + gp;
                a[mt][0] = fb(As[ra * GA_ST + kk + tg]);
                a[mt][1] = fb(As[(ra + 8) * GA_ST + kk + tg]);
                a[mt][2] = fb(As[ra * GA_ST + kk + tg + 4]);
                a[mt][3] = fb(As[(ra + 8) * GA_ST + kk + tg + 4]);
            }
            #pragma unroll
            for (int nt = 0; nt < 4; nt++) {
                int nb = (wn << 5) + (nt << 3) + gp;
                uint32_t b0 = fb(Bs[(kk + tg) * GB_ST + nb]);
                uint32_t b1 = fb(Bs[(kk + tg + 4) * GB_ST + nb]);
                #pragma unroll
                for (int mt = 0; mt < 4; mt++)
                    mma_tf32(acc[mt][nt], a[mt][0], a[mt][1], a[mt][2], a[mt][3], b0, b1);
            }
        }
        __syncthreads();
    }

    #pragma unroll
    for (int mt = 0; mt < 4; mt++) {
        int row = row0 + (wm << 6) + (mt << 4) + gp;
        #pragma unroll
        for (int nt = 0; nt < 4; nt++) {
            int col = col0 + (wn << 5) + (nt << 3) + (tg << 1);
            if (col < N) {
                *reinterpret_cast<float2*>(&C[(size_t)row * N + col]) =
                    make_float2(acc[mt][nt][0], acc[mt][nt][1]);
                *reinterpret_cast<float2*>(&C[(size_t)(row + 8) * N + col]) =
                    make_float2(acc[mt][nt][2], acc[mt][nt][3]);
            }
        }
    }
}

// ---------------- RMSNorm ----------------------------------------------------
__global__ __launch_bounds__(256) void rmsnorm_kernel(
    const float* __restrict__ in, const float* __restrict__ w,
    float* __restrict__ out, int in_stride, int out_stride, int n)
{
    const int row = blockIdx.x;
    const float* x = in + (size_t)row * in_stride;
    float ss = 0.f;
    for (int j = threadIdx.x; j < n; j += 256) { float v = x[j]; ss += v * v; }
    __shared__ float red[8];
    #pragma unroll
    for (int off = 16; off; off >>= 1) ss += __shfl_xor_sync(~0u, ss, off);
    if ((threadIdx.x & 31) == 0) red[threadIdx.x >> 5] = ss;
    __syncthreads();
    if (threadIdx.x == 0) {
        float t = 0.f;
        #pragma unroll
        for (int i = 0; i < 8; i++) t += red[i];
        red[0] = rsqrtf(t / n + 1e-6f);
    }
    __syncthreads();
    const float r = red[0];
    float* y = out + (size_t)row * out_stride;
    for (int j = threadIdx.x; j < n; j += 256) y[j] = w[j] * x[j] * r;
}

// ---------------- RoPE -------------------------------------------------------
__global__ void rope_q_kernel(float* __restrict__ q,
                              const float* __restrict__ cosb,
                              const float* __restrict__ sinb)
{
    const int t = blockIdx.x;
    const int h = threadIdx.x >> 5;
    const int i = threadIdx.x & 31;
    const int s = t & (S_LEN - 1);
    const float cv = cosb[s * DR + 2 * i];
    const float sv = sinb[s * DR + 2 * i];
    float* p = q + (size_t)t * NH * DQK + h * DQK + DN + 2 * i;
    const float xr = p[0], xi = p[1];
    p[0] = xr * cv - xi * sv;
    p[1] = xr * sv + xi * cv;
}

__global__ void rope_k_kernel(const float* __restrict__ ckv,
                              const float* __restrict__ cosb,
                              const float* __restrict__ sinb,
                              float* __restrict__ kr)
{
    const int t = blockIdx.x;
    const int i = threadIdx.x;
    const int s = t & (S_LEN - 1);
    const float cv = cosb[s * DR + 2 * i];
    const float sv = sinb[s * DR + 2 * i];
    const float xr = ckv[(size_t)t * CKV_W + KVL + 2 * i];
    const float xi = ckv[(size_t)t * CKV_W + KVL + 2 * i + 1];
    kr[t * DR + 2 * i]     = xr * cv - xi * sv;
    kr[t * DR + 2 * i + 1] = xr * sv + xi * cv;
}

// ---------------- Flash attention, TF32 mma ----------------------------------
// BM=128 (8 warps x 16 rows), BN=64, D=192. grid (16, 32), 256 threads.
#define AQ_ST 196   // 196 % 32 == 4  (A-frag pattern)
#define AK_ST 196   // K rows indexed by group -> A-type pattern, 4 mod 32 OK
#define AV_ST 136   // 136 % 32 == 8  (B-frag pattern)
#define AP_ST 68    // 68  % 32 == 4  (A-frag pattern)
#define SM_Q 0
#define SM_K (128 * AQ_ST)
#define SM_V (SM_K + 64 * AK_ST)
#define SM_P (SM_V + 64 * AV_ST)
#define ATTN_SMEM_BYTES ((SM_P + 128 * AP_ST) * 4)

__global__ __launch_bounds__(256) void attn_tf32_kernel(
    const float* __restrict__ q, const float* __restrict__ kv,
    const float* __restrict__ kr, float* __restrict__ ao)
{
    extern __shared__ float sm[];
    float* Qs = sm + SM_Q;
    float* Ks = sm + SM_K;
    float* Vs = sm + SM_V;
    float* Ps = sm + SM_P;

    const int tid = threadIdx.x;
    const int wid = tid >> 5, lane = tid & 31;
    const int tg = lane & 3, gp = lane >> 2;
    const int r0 = wid << 4;                    // warp row base in [0,128)
    const int bh = blockIdx.y;
    const int b = bh >> 4, h = bh & 15;
    const int q0 = blockIdx.x << 7;
    const size_t tokbase = (size_t)b * S_LEN;
    const float scale = rsqrtf((float)DQK);

    // stage Q tile [128][192] (tf32)
    for (int f = tid; f < 128 * 48; f += 256) {
        int r = f / 48, dq = (f % 48) << 2;
        float4 v = *reinterpret_cast<const float4*>(
            &q[(tokbase + q0 + r) * (NH * DQK) + h * DQK + dq]);
        v.x = to_tf32(v.x); v.y = to_tf32(v.y);
        v.z = to_tf32(v.z); v.w = to_tf32(v.w);
        *reinterpret_cast<float4*>(&Qs[r * AQ_ST + dq]) = v;
    }

    float m_[2] = {-1e30f, -1e30f};
    float l_[2] = {0.f, 0.f};
    float o[16][4];
    #pragma unroll
    for (int nt = 0; nt < 16; nt++)
        #pragma unroll
        for (int r = 0; r < 4; r++) o[nt][r] = 0.f;

    for (int kb = 0; kb < S_LEN; kb += 64) {
        __syncthreads();
        // stage K tile [64][192]: nope from kv, rope from kr
        for (int f = tid; f < 64 * 48; f += 256) {
            int r = f / 48, dq = (f % 48) << 2;
            float4 v;
            if (dq < DN)
                v = *reinterpret_cast<const float4*>(
                    &kv[(tokbase + kb + r) * (NH * 256) + h * 256 + dq]);
            else
                v = *reinterpret_cast<const float4*>(
                    &kr[(tokbase + kb + r) * DR + (dq - DN)]);
            v.x = to_tf32(v.x); v.y = to_tf32(v.y);
            v.z = to_tf32(v.z); v.w = to_tf32(v.w);
            *reinterpret_cast<float4*>(&Ks[r * AK_ST + dq]) = v;
        }
        // stage V tile [64][128]
        for (int f = tid; f < 64 * 32; f += 256) {
            int r = f >> 5, dq = (f & 31) << 2;
            float4 v = *reinterpret_cast<const float4*>(
                &kv[(tokbase + kb + r) * (NH * 256) + h * 256 + DN + dq]);
            v.x = to_tf32(v.x); v.y = to_tf32(v.y);
            v.z = to_tf32(v.z); v.w = to_tf32(v.w);
            *reinterpret_cast<float4*>(&Vs[r * AV_ST + dq]) = v;
        }
        __syncthreads();

        // ---- S = Q @ K^T : warp computes 16x64 ----
        float s[8][4];
        #pragma unroll
        for (int nt = 0; nt < 8; nt++)
            #pragma unroll
            for (int r = 0; r < 4; r++) s[nt][r] = 0.f;

        #pragma unroll
        for (int ks = 0; ks < 24; ks++) {
            const int kk = ks << 3;
            const int ra = r0 + gp;
            uint32_t a0 = fb(Qs[ra * AQ_ST + kk + tg]);
            uint32_t a1 = fb(Qs[(ra + 8) * AQ_ST + kk + tg]);
            uint32_t a2 = fb(Qs[ra * AQ_ST + kk + tg + 4]);
            uint32_t a3 = fb(Qs[(ra + 8) * AQ_ST + kk + tg + 4]);
            #pragma unroll
            for (int nt = 0; nt < 8; nt++) {
                int kvp = (nt << 3) + gp;
                uint32_t b0 = fb(Ks[kvp * AK_ST + kk + tg]);
                uint32_t b1 = fb(Ks[kvp * AK_ST + kk + tg + 4]);
                mma_tf32(s[nt], a0, a1, a2, a3, b0, b1);
            }
        }

        // ---- online softmax (2 rows per thread: r0+gp, r0+gp+8) ----
        #pragma unroll
        for (int hr = 0; hr < 2; hr++) {
            float mx = -1e30f;
            #pragma unroll
            for (int nt = 0; nt < 8; nt++) {
                s[nt][2 * hr]     *= scale;
                s[nt][2 * hr + 1] *= scale;
                mx = fmaxf(mx, fmaxf(s[nt][2 * hr], s[nt][2 * hr + 1]));
            }
            mx = fmaxf(mx, __shfl_xor_sync(~0u, mx, 1));
            mx = fmaxf(mx, __shfl_xor_sync(~0u, mx, 2));
            float nm = fmaxf(m_[hr], mx);
            float alpha = __expf(m_[hr] - nm);
            float ls = 0.f;
            #pragma unroll
            for (int nt = 0; nt < 8; nt++) {
                float p0 = __expf(s[nt][2 * hr] - nm);
                float p1 = __expf(s[nt][2 * hr + 1] - nm);
                s[nt][2 * hr] = p0; s[nt][2 * hr + 1] = p1;
                ls += p0 + p1;
            }
            ls += __shfl_xor_sync(~0u, ls, 1);
            ls += __shfl_xor_sync(~0u, ls, 2);
            l_[hr] = l_[hr] * alpha + ls;
            m_[hr] = nm;
            #pragma unroll
            for (int nt = 0; nt < 16; nt++) {
                o[nt][2 * hr]     *= alpha;
                o[nt][2 * hr + 1] *= alpha;
            }
            // write P (tf32) to this warp's rows
            int pr = r0 + gp + (hr << 3);
            #pragma unroll
            for (int nt = 0; nt < 8; nt++) {
                Ps[pr * AP_ST + (nt << 3) + (tg << 1)]     = to_tf32(s[nt][2 * hr]);
                Ps[pr * AP_ST + (nt << 3) + (tg << 1) + 1] = to_tf32(s[nt][2 * hr + 1]);
            }
        }
        __syncwarp();

        // ---- O += P @ V : warp 16x128 ----
        #pragma unroll
        for (int ks = 0; ks < 8; ks++) {
            const int kk = ks << 3;
            const int ra = r0 + gp;
            uint32_t a0 = fb(Ps[ra * AP_ST + kk + tg]);
            uint32_t a1 = fb(Ps[(ra + 8) * AP_ST + kk + tg]);
            uint32_t a2 = fb(Ps[ra * AP_ST + kk + tg + 4]);
            uint32_t a3 = fb(Ps[(ra + 8) * AP_ST + kk + tg + 4]);
            #pragma unroll
            for (int nt = 0; nt < 16; nt++) {
                int nb = (nt << 3) + gp;
                uint32_t b0 = fb(Vs[(kk + tg) * AV_ST + nb]);
                uint32_t b1 = fb(Vs[(kk + tg + 4) * AV_ST + nb]);
                mma_tf32(o[nt], a0, a1, a2, a3, b0, b1);
            }
        }
    }

    // epilogue
    float inv0 = 1.0f / l_[0], inv1 = 1.0f / l_[1];
    size_t rlo = (tokbase + q0 + r0 + gp) * (size_t)(NH * DVV) + h * DVV;
    size_t rhi = (tokbase + q0 + r0 + gp + 8) * (size_t)(NH * DVV) + h * DVV;
    #pragma unroll
    for (int nt = 0; nt < 16; nt++) {
        int col = (nt << 3) + (tg << 1);
        *reinterpret_cast<float2*>(&ao[rlo + col]) =
            make_float2(o[nt][0] * inv0, o[nt][1] * inv0);
        *reinterpret_cast<float2*>(&ao[rhi + col]) =
            make_float2(o[nt][2] * inv1, o[nt][3] * inv1);
    }
}

// ---------------- launch -----------------------------------------------------
extern "C" void kernel_launch(void* const* d_in, const int* in_sizes, int n_in,
                              void* d_out, int out_size)
{
    const float* hidden  = (const float*)d_in[0];
    const float* cosb    = (const float*)d_in[1];
    const float* sinb    = (const float*)d_in[2];
    const float* q_a_w   = (const float*)d_in[3];
    const float* q_a_ln  = (const float*)d_in[4];
    const float* q_b_w   = (const float*)d_in[5];
    const float* kv_a_w  = (const float*)d_in[6];
    const float* kv_a_ln = (const float*)d_in[7];
    const float* kv_b_w  = (const float*)d_in[8];
    const float* o_w     = (const float*)d_in[9];
    float* out = (float*)d_out;

    float *qa, *qq, *ckv, *ckn, *kvf, *kr, *ao;
    cudaGetSymbolAddress((void**)&qa,  g_qa);
    cudaGetSymbolAddress((void**)&qq,  g_q);
    cudaGetSymbolAddress((void**)&ckv, g_ckv);
    cudaGetSymbolAddress((void**)&ckn, g_ckn);
    cudaGetSymbolAddress((void**)&kvf, g_kv);
    cudaGetSymbolAddress((void**)&kr,  g_kr);
    cudaGetSymbolAddress((void**)&ao,  g_ao);

    cudaFuncSetAttribute(attn_tf32_kernel,
        cudaFuncAttributeMaxDynamicSharedMemorySize, ATTN_SMEM_BYTES);

    // 1) q_a = hidden @ q_a_w
    gemm_tf32<<<dim3(QL / 128, NTOK / 128), 256>>>(hidden, q_a_w, qa, NTOK, QL, HID);
    // 2) ckv = hidden @ kv_a_w
    gemm_tf32<<<dim3((CKV_W + 127) / 128, NTOK / 128), 256>>>(hidden, kv_a_w, ckv, NTOK, CKV_W, HID);
    // 3) rmsnorm q_a (in place)
    rmsnorm_kernel<<<NTOK, 256>>>(qa, q_a_ln, qa, QL, QL, QL);
    // 4) rmsnorm compressed_kv -> ckn
    rmsnorm_kernel<<<NTOK, 256>>>(ckv, kv_a_ln, ckn, CKV_W, KVL, KVL);
    // 5) q = qa_n @ q_b_w
    gemm_tf32<<<dim3((NH * DQK) / 128, NTOK / 128), 256>>>(qa, q_b_w, qq, NTOK, NH * DQK, QL);
    // 6) kv = ckn @ kv_b_w
    gemm_tf32<<<dim3((NH * 256) / 128, NTOK / 128), 256>>>(ckn, kv_b_w, kvf, NTOK, NH * 256, KVL);
    // 7) rope q (in place)
    rope_q_kernel<<<NTOK, NH * 32>>>(qq, cosb, sinb);
    // 8) rope k_rope -> kr
    rope_k_kernel<<<NTOK, 32>>>(ckv, cosb, sinb, kr);
    // 9) attention
    attn_tf32_kernel<<<dim3(S_LEN / 128, BATCH * NH), 256, ATTN_SMEM_BYTES>>>(qq, kvf, kr, ao);
    // 10) out = ao @ o_w
    gemm_tf32<<<dim3(HID / 128, NTOK / 128), 256>>>(ao, o_w, out, NTOK, HID, HID);
}

// round 4
// speedup vs baseline: 4.2852x; 1.1194x over previous
#include <cuda_runtime.h>
#include <math.h>
#include <stdint.h>

#define S_LEN   2048
#define BATCH   2
#define NH      16
#define HID     2048
#define QL      1536
#define KVL     512
#define DR      64
#define DN      128
#define DVV     128
#define DQK     192
#define NTOK    (BATCH * S_LEN)     // 4096
#define CKV_W   (KVL + DR)          // 576

// ---------------- scratch (static device globals) ---------------------------
__device__ float g_qa [NTOK * QL];
__device__ float g_q  [NTOK * NH * DQK];
__device__ float g_ckv[NTOK * CKV_W];
__device__ float g_ckn[NTOK * KVL];
__device__ float g_kv [NTOK * NH * 256];
__device__ float g_kr [NTOK * DR];
__device__ float g_ao [NTOK * NH * DVV];
// tf32-rounded copies of inputs
__device__ float g_hid [NTOK * HID];
__device__ float g_wqa [HID * QL];
__device__ float g_wqb [QL * NH * DQK];
__device__ float g_wkva[HID * CKV_W];
__device__ float g_wkvb[KVL * NH * 256];
__device__ float g_wo  [NH * DVV * HID];

// ---------------- helpers ----------------------------------------------------
__device__ __forceinline__ float to_tf32(float x) {
    uint32_t u;
    asm("cvt.rna.tf32.f32 %0, %1;" : "=r"(u) : "f"(x));
    return __uint_as_float(u);
}
__device__ __forceinline__ uint32_t fb(float x) { return __float_as_uint(x); }

__device__ __forceinline__ void mma_tf32(float (&c)[4],
    uint32_t a0, uint32_t a1, uint32_t a2, uint32_t a3,
    uint32_t b0, uint32_t b1)
{
    asm volatile(
        "mma.sync.aligned.m16n8k8.row.col.f32.tf32.tf32.f32 "
        "{%0,%1,%2,%3},{%4,%5,%6,%7},{%8,%9},{%0,%1,%2,%3};"
        : "+f"(c[0]), "+f"(c[1]), "+f"(c[2]), "+f"(c[3])
        : "r"(a0), "r"(a1), "r"(a2), "r"(a3), "r"(b0), "r"(b1));
}

__device__ __forceinline__ void cp16(float* dst_smem, const float* src, bool valid) {
    uint32_t d = (uint32_t)__cvta_generic_to_shared(dst_smem);
    int sz = valid ? 16 : 0;
    asm volatile("cp.async.cg.shared.global [%0], [%1], 16, %2;\n"
                 :: "r"(d), "l"(src), "r"(sz));
}
__device__ __forceinline__ void cp_commit() {
    asm volatile("cp.async.commit_group;\n");
}
__device__ __forceinline__ void cp_wait1() {
    asm volatile("cp.async.wait_group 1;\n");
}

// ---------------- pre-round pass ---------------------------------------------
__global__ void round_copy(const float* __restrict__ in, float* __restrict__ out, int n4)
{
    int i = blockIdx.x * blockDim.x + threadIdx.x;
    if (i < n4) {
        float4 v = reinterpret_cast<const float4*>(in)[i];
        v.x = to_tf32(v.x); v.y = to_tf32(v.y);
        v.z = to_tf32(v.z); v.w = to_tf32(v.w);
        reinterpret_cast<float4*>(out)[i] = v;
    }
}

// ---------------- TF32 GEMM, cp.async double-buffered ------------------------
// C[M,N] = A[M,K] @ B[K,N]. 128x128 block, BK=16, 256 threads,
// warp grid 2(M)x4(N), warp tile 64x32. A,B must be pre-rounded to tf32.
#define GA_ST 20    // 20 % 32 == 20 -> A-frag scalar loads conflict-free
#define GB_ST 136   // 136 % 32 == 8 -> B-frag scalar loads conflict-free

__global__ __launch_bounds__(256) void gemm_db(
    const float* __restrict__ A, const float* __restrict__ B,
    float* __restrict__ C, int M, int N, int K, int round_out)
{
    __shared__ float As[2][128 * GA_ST];
    __shared__ float Bs[2][16 * GB_ST];
    const int tid = threadIdx.x;
    const int wid = tid >> 5, lane = tid & 31;
    const int wm = wid >> 2, wn = wid & 3;
    const int row0 = blockIdx.y << 7;
    const int col0 = blockIdx.x << 7;
    const int tg = lane & 3, gp = lane >> 2;

    // copy coordinates (2 float4 for A + 2 for B per thread per stage)
    const int am0 = tid >> 2, akq = (tid & 3) << 2;            // A: f = tid, tid+256
    const int bk0 = tid >> 5, bc = (tid & 31) << 2;            // B: f = tid, tid+256

    float acc[4][4][4];
    #pragma unroll
    for (int mt = 0; mt < 4; mt++)
        #pragma unroll
        for (int nt = 0; nt < 4; nt++)
            #pragma unroll
            for (int r = 0; r < 4; r++) acc[mt][nt][r] = 0.f;

    // ---- stage k0 = 0 into buffer 0 ----
    {
        cp16(&As[0][am0 * GA_ST + akq],        &A[(size_t)(row0 + am0) * K + akq],        true);
        cp16(&As[0][(am0 + 64) * GA_ST + akq], &A[(size_t)(row0 + am0 + 64) * K + akq],   true);
        cp16(&Bs[0][bk0 * GB_ST + bc],         &B[(size_t)bk0 * N + col0 + bc],           col0 + bc < N);
        cp16(&Bs[0][(bk0 + 8) * GB_ST + bc],   &B[(size_t)(bk0 + 8) * N + col0 + bc],     col0 + bc < N);
        cp_commit();
    }

    int buf = 0;
    for (int k0 = 0; k0 < K; k0 += 16) {
        const int nk = k0 + 16;
        if (nk < K) {
            float* as = As[buf ^ 1];
            float* bs = Bs[buf ^ 1];
            cp16(&as[am0 * GA_ST + akq],        &A[(size_t)(row0 + am0) * K + nk + akq],      true);
            cp16(&as[(am0 + 64) * GA_ST + akq], &A[(size_t)(row0 + am0 + 64) * K + nk + akq], true);
            cp16(&bs[bk0 * GB_ST + bc],         &B[(size_t)(nk + bk0) * N + col0 + bc],       col0 + bc < N);
            cp16(&bs[(bk0 + 8) * GB_ST + bc],   &B[(size_t)(nk + bk0 + 8) * N + col0 + bc],   col0 + bc < N);
        }
        cp_commit();
        cp_wait1();
        __syncthreads();

        const float* as = As[buf];
        const float* bs = Bs[buf];
        #pragma unroll
        for (int ks = 0; ks < 2; ks++) {
            const int kk = ks << 3;
            uint32_t a[4][4];
            #pragma unroll
            for (int mt = 0; mt < 4; mt++) {
                int ra = (wm << 6) + (mt << 4) + gp;
                a[mt][0] = fb(as[ra * GA_ST + kk + tg]);
                a[mt][1] = fb(as[(ra + 8) * GA_ST + kk + tg]);
                a[mt][2] = fb(as[ra * GA_ST + kk + tg + 4]);
                a[mt][3] = fb(as[(ra + 8) * GA_ST + kk + tg + 4]);
            }
            #pragma unroll
            for (int nt = 0; nt < 4; nt++) {
                int nb = (wn << 5) + (nt << 3) + gp;
                uint32_t b0 = fb(bs[(kk + tg) * GB_ST + nb]);
                uint32_t b1 = fb(bs[(kk + tg + 4) * GB_ST + nb]);
                #pragma unroll
                for (int mt = 0; mt < 4; mt++)
                    mma_tf32(acc[mt][nt], a[mt][0], a[mt][1], a[mt][2], a[mt][3], b0, b1);
            }
        }
        __syncthreads();
        buf ^= 1;
    }

    #pragma unroll
    for (int mt = 0; mt < 4; mt++) {
        int row = row0 + (wm << 6) + (mt << 4) + gp;
        #pragma unroll
        for (int nt = 0; nt < 4; nt++) {
            int col = col0 + (wn << 5) + (nt << 3) + (tg << 1);
            if (col < N) {
                float2 lo = make_float2(acc[mt][nt][0], acc[mt][nt][1]);
                float2 hi = make_float2(acc[mt][nt][2], acc[mt][nt][3]);
                if (round_out) {
                    lo.x = to_tf32(lo.x); lo.y = to_tf32(lo.y);
                    hi.x = to_tf32(hi.x); hi.y = to_tf32(hi.y);
                }
                *reinterpret_cast<float2*>(&C[(size_t)row * N + col]) = lo;
                *reinterpret_cast<float2*>(&C[(size_t)(row + 8) * N + col]) = hi;
            }
        }
    }
}

// ---------------- RMSNorm (writes tf32-rounded) -------------------------------
__global__ __launch_bounds__(256) void rmsnorm_kernel(
    const float* __restrict__ in, const float* __restrict__ w,
    float* __restrict__ out, int in_stride, int out_stride, int n)
{
    const int row = blockIdx.x;
    const float* x = in + (size_t)row * in_stride;
    float ss = 0.f;
    for (int j = threadIdx.x; j < n; j += 256) { float v = x[j]; ss += v * v; }
    __shared__ float red[8];
    #pragma unroll
    for (int off = 16; off; off >>= 1) ss += __shfl_xor_sync(~0u, ss, off);
    if ((threadIdx.x & 31) == 0) red[threadIdx.x >> 5] = ss;
    __syncthreads();
    if (threadIdx.x == 0) {
        float t = 0.f;
        #pragma unroll
        for (int i = 0; i < 8; i++) t += red[i];
        red[0] = rsqrtf(t / n + 1e-6f);
    }
    __syncthreads();
    const float r = red[0];
    float* y = out + (size_t)row * out_stride;
    for (int j = threadIdx.x; j < n; j += 256) y[j] = to_tf32(w[j] * x[j] * r);
}

// ---------------- RoPE (writes tf32-rounded) ----------------------------------
__global__ void rope_q_kernel(float* __restrict__ q,
                              const float* __restrict__ cosb,
                              const float* __restrict__ sinb)
{
    const int t = blockIdx.x;
    const int h = threadIdx.x >> 5;
    const int i = threadIdx.x & 31;
    const int s = t & (S_LEN - 1);
    const float cv = cosb[s * DR + 2 * i];
    const float sv = sinb[s * DR + 2 * i];
    float* p = q + (size_t)t * NH * DQK + h * DQK + DN + 2 * i;
    const float xr = p[0], xi = p[1];
    p[0] = to_tf32(xr * cv - xi * sv);
    p[1] = to_tf32(xr * sv + xi * cv);
}

__global__ void rope_k_kernel(const float* __restrict__ ckv,
                              const float* __restrict__ cosb,
                              const float* __restrict__ sinb,
                              float* __restrict__ kr)
{
    const int t = blockIdx.x;
    const int i = threadIdx.x;
    const int s = t & (S_LEN - 1);
    const float cv = cosb[s * DR + 2 * i];
    const float sv = sinb[s * DR + 2 * i];
    const float xr = ckv[(size_t)t * CKV_W + KVL + 2 * i];
    const float xi = ckv[(size_t)t * CKV_W + KVL + 2 * i + 1];
    kr[t * DR + 2 * i]     = to_tf32(xr * cv - xi * sv);
    kr[t * DR + 2 * i + 1] = to_tf32(xr * sv + xi * cv);
}

// ---------------- Flash attention, TF32 mma (inputs pre-rounded) --------------
#define AQ_ST 196
#define AK_ST 196
#define AV_ST 136
#define AP_ST 68
#define SM_Q 0
#define SM_K (128 * AQ_ST)
#define SM_V (SM_K + 64 * AK_ST)
#define SM_P (SM_V + 64 * AV_ST)
#define ATTN_SMEM_BYTES ((SM_P + 128 * AP_ST) * 4)

__global__ __launch_bounds__(256) void attn_tf32_kernel(
    const float* __restrict__ q, const float* __restrict__ kv,
    const float* __restrict__ kr, float* __restrict__ ao)
{
    extern __shared__ float sm[];
    float* Qs = sm + SM_Q;
    float* Ks = sm + SM_K;
    float* Vs = sm + SM_V;
    float* Ps = sm + SM_P;

    const int tid = threadIdx.x;
    const int wid = tid >> 5, lane = tid & 31;
    const int tg = lane & 3, gp = lane >> 2;
    const int r0 = wid << 4;
    const int bh = blockIdx.y;
    const int b = bh >> 4, h = bh & 15;
    const int q0 = blockIdx.x << 7;
    const size_t tokbase = (size_t)b * S_LEN;
    const float scale = rsqrtf((float)DQK);

    for (int f = tid; f < 128 * 48; f += 256) {
        int r = f / 48, dq = (f % 48) << 2;
        *reinterpret_cast<float4*>(&Qs[r * AQ_ST + dq]) =
            *reinterpret_cast<const float4*>(
                &q[(tokbase + q0 + r) * (NH * DQK) + h * DQK + dq]);
    }

    float m_[2] = {-1e30f, -1e30f};
    float l_[2] = {0.f, 0.f};
    float o[16][4];
    #pragma unroll
    for (int nt = 0; nt < 16; nt++)
        #pragma unroll
        for (int r = 0; r < 4; r++) o[nt][r] = 0.f;

    for (int kb = 0; kb < S_LEN; kb += 64) {
        __syncthreads();
        for (int f = tid; f < 64 * 48; f += 256) {
            int r = f / 48, dq = (f % 48) << 2;
            float4 v;
            if (dq < DN)
                v = *reinterpret_cast<const float4*>(
                    &kv[(tokbase + kb + r) * (NH * 256) + h * 256 + dq]);
            else
                v = *reinterpret_cast<const float4*>(
                    &kr[(tokbase + kb + r) * DR + (dq - DN)]);
            *reinterpret_cast<float4*>(&Ks[r * AK_ST + dq]) = v;
        }
        for (int f = tid; f < 64 * 32; f += 256) {
            int r = f >> 5, dq = (f & 31) << 2;
            *reinterpret_cast<float4*>(&Vs[r * AV_ST + dq]) =
                *reinterpret_cast<const float4*>(
                    &kv[(tokbase + kb + r) * (NH * 256) + h * 256 + DN + dq]);
        }
        __syncthreads();

        float s[8][4];
        #pragma unroll
        for (int nt = 0; nt < 8; nt++)
            #pragma unroll
            for (int r = 0; r < 4; r++) s[nt][r] = 0.f;

        #pragma unroll
        for (int ks = 0; ks < 24; ks++) {
            const int kk = ks << 3;
            const int ra = r0 + gp;
            uint32_t a0 = fb(Qs[ra * AQ_ST + kk + tg]);
            uint32_t a1 = fb(Qs[(ra + 8) * AQ_ST + kk + tg]);
            uint32_t a2 = fb(Qs[ra * AQ_ST + kk + tg + 4]);
            uint32_t a3 = fb(Qs[(ra + 8) * AQ_ST + kk + tg + 4]);
            #pragma unroll
            for (int nt = 0; nt < 8; nt++) {
                int kvp = (nt << 3) + gp;
                uint32_t b0 = fb(Ks[kvp * AK_ST + kk + tg]);
                uint32_t b1 = fb(Ks[kvp * AK_ST + kk + tg + 4]);
                mma_tf32(s[nt], a0, a1, a2, a3, b0, b1);
            }
        }

        #pragma unroll
        for (int hr = 0; hr < 2; hr++) {
            float mx = -1e30f;
            #pragma unroll
            for (int nt = 0; nt < 8; nt++) {
                s[nt][2 * hr]     *= scale;
                s[nt][2 * hr + 1] *= scale;
                mx = fmaxf(mx, fmaxf(s[nt][2 * hr], s[nt][2 * hr + 1]));
            }
            mx = fmaxf(mx, __shfl_xor_sync(~0u, mx, 1));
            mx = fmaxf(mx, __shfl_xor_sync(~0u, mx, 2));
            float nm = fmaxf(m_[hr], mx);
            float alpha = __expf(m_[hr] - nm);
            float ls = 0.f;
            #pragma unroll
            for (int nt = 0; nt < 8; nt++) {
                float p0 = __expf(s[nt][2 * hr] - nm);
                float p1 = __expf(s[nt][2 * hr + 1] - nm);
                s[nt][2 * hr] = p0; s[nt][2 * hr + 1] = p1;
                ls += p0 + p1;
            }
            ls += __shfl_xor_sync(~0u, ls, 1);
            ls += __shfl_xor_sync(~0u, ls, 2);
            l_[hr] = l_[hr] * alpha + ls;
            m_[hr] = nm;
            #pragma unroll
            for (int nt = 0; nt < 16; nt++) {
                o[nt][2 * hr]     *= alpha;
                o[nt][2 * hr + 1] *= alpha;
            }
            int pr = r0 + gp + (hr << 3);
            #pragma unroll
            for (int nt = 0; nt < 8; nt++) {
                Ps[pr * AP_ST + (nt << 3) + (tg << 1)]     = to_tf32(s[nt][2 * hr]);
                Ps[pr * AP_ST + (nt << 3) + (tg << 1) + 1] = to_tf32(s[nt][2 * hr + 1]);
            }
        }
        __syncwarp();

        #pragma unroll
        for (int ks = 0; ks < 8; ks++) {
            const int kk = ks << 3;
            const int ra = r0 + gp;
            uint32_t a0 = fb(Ps[ra * AP_ST + kk + tg]);
            uint32_t a1 = fb(Ps[(ra + 8) * AP_ST + kk + tg]);
            uint32_t a2 = fb(Ps[ra * AP_ST + kk + tg + 4]);
            uint32_t a3 = fb(Ps[(ra + 8) * AP_ST + kk + tg + 4]);
            #pragma unroll
            for (int nt = 0; nt < 16; nt++) {
                int nb = (nt << 3) + gp;
                uint32_t b0 = fb(Vs[(kk + tg) * AV_ST + nb]);
                uint32_t b1 = fb(Vs[(kk + tg + 4) * AV_ST + nb]);
                mma_tf32(o[nt], a0, a1, a2, a3, b0, b1);
            }
        }
    }

    float inv0 = 1.0f / l_[0], inv1 = 1.0f / l_[1];
    size_t rlo = (tokbase + q0 + r0 + gp) * (size_t)(NH * DVV) + h * DVV;
    size_t rhi = (tokbase + q0 + r0 + gp + 8) * (size_t)(NH * DVV) + h * DVV;
    #pragma unroll
    for (int nt = 0; nt < 16; nt++) {
        int col = (nt << 3) + (tg << 1);
        *reinterpret_cast<float2*>(&ao[rlo + col]) =
            make_float2(to_tf32(o[nt][0] * inv0), to_tf32(o[nt][1] * inv0));
        *reinterpret_cast<float2*>(&ao[rhi + col]) =
            make_float2(to_tf32(o[nt][2] * inv1), to_tf32(o[nt][3] * inv1));
    }
}

// ---------------- launch ------------------------------------------------------
extern "C" void kernel_launch(void* const* d_in, const int* in_sizes, int n_in,
                              void* d_out, int out_size)
{
    const float* hidden  = (const float*)d_in[0];
    const float* cosb    = (const float*)d_in[1];
    const float* sinb    = (const float*)d_in[2];
    const float* q_a_w   = (const float*)d_in[3];
    const float* q_a_ln  = (const float*)d_in[4];
    const float* q_b_w   = (const float*)d_in[5];
    const float* kv_a_w  = (const float*)d_in[6];
    const float* kv_a_ln = (const float*)d_in[7];
    const float* kv_b_w  = (const float*)d_in[8];
    const float* o_w     = (const float*)d_in[9];
    float* out = (float*)d_out;

    float *qa, *qq, *ckv, *ckn, *kvf, *kr, *ao;
    float *hid, *wqa, *wqb, *wkva, *wkvb, *wo;
    cudaGetSymbolAddress((void**)&qa,   g_qa);
    cudaGetSymbolAddress((void**)&qq,   g_q);
    cudaGetSymbolAddress((void**)&ckv,  g_ckv);
    cudaGetSymbolAddress((void**)&ckn,  g_ckn);
    cudaGetSymbolAddress((void**)&kvf,  g_kv);
    cudaGetSymbolAddress((void**)&kr,   g_kr);
    cudaGetSymbolAddress((void**)&ao,   g_ao);
    cudaGetSymbolAddress((void**)&hid,  g_hid);
    cudaGetSymbolAddress((void**)&wqa,  g_wqa);
    cudaGetSymbolAddress((void**)&wqb,  g_wqb);
    cudaGetSymbolAddress((void**)&wkva, g_wkva);
    cudaGetSymbolAddress((void**)&wkvb, g_wkvb);
    cudaGetSymbolAddress((void**)&wo,   g_wo);

    cudaFuncSetAttribute(attn_tf32_kernel,
        cudaFuncAttributeMaxDynamicSharedMemorySize, ATTN_SMEM_BYTES);

    // 0) pre-round inputs to tf32
    {
        struct { const float* in; float* out; int n; } cps[6] = {
            {hidden, hid,  NTOK * HID},
            {q_a_w,  wqa,  HID * QL},
            {q_b_w,  wqb,  QL * NH * DQK},
            {kv_a_w, wkva, HID * CKV_W},
            {kv_b_w, wkvb, KVL * NH * 256},
            {o_w,    wo,   NH * DVV * HID},
        };
        for (int i = 0; i < 6; i++) {
            int n4 = cps[i].n >> 2;
            round_copy<<<(n4 + 255) / 256, 256>>>(cps[i].in, cps[i].out, n4);
        }
    }

    // 1) q_a = hid @ wqa   (round out -> feeds rmsnorm/gemm)
    gemm_db<<<dim3(QL / 128, NTOK / 128), 256>>>(hid, wqa, qa, NTOK, QL, HID, 1);
    // 2) ckv = hid @ wkva
    gemm_db<<<dim3((CKV_W + 127) / 128, NTOK / 128), 256>>>(hid, wkva, ckv, NTOK, CKV_W, HID, 1);
    // 3) rmsnorm q_a (in place, rounded)
    rmsnorm_kernel<<<NTOK, 256>>>(qa, q_a_ln, qa, QL, QL, QL);
    // 4) rmsnorm compressed_kv -> ckn (rounded)
    rmsnorm_kernel<<<NTOK, 256>>>(ckv, kv_a_ln, ckn, CKV_W, KVL, KVL);
    // 5) q = qa @ wqb (rounded)
    gemm_db<<<dim3((NH * DQK) / 128, NTOK / 128), 256>>>(qa, wqb, qq, NTOK, NH * DQK, QL, 1);
    // 6) kv = ckn @ wkvb (rounded)
    gemm_db<<<dim3((NH * 256) / 128, NTOK / 128), 256>>>(ckn, wkvb, kvf, NTOK, NH * 256, KVL, 1);
    // 7) rope q (in place, rounded)
    rope_q_kernel<<<NTOK, NH * 32>>>(qq, cosb, sinb);
    // 8) rope k_rope -> kr (rounded)
    rope_k_kernel<<<NTOK, 32>>>(ckv, cosb, sinb, kr);
    // 9) attention (inputs pre-rounded; output rounded for final gemm)
    attn_tf32_kernel<<<dim3(S_LEN / 128, BATCH * NH), 256, ATTN_SMEM_BYTES>>>(qq, kvf, kr, ao);
    // 10) out = ao @ wo  (fp32 output, NOT rounded)
    gemm_db<<<dim3(HID / 128, NTOK / 128), 256>>>(ao, wo, out, NTOK, HID, HID, 0);
}

// round 8
// speedup vs baseline: 7.5357x; 1.7585x over previous
#include <cuda_runtime.h>
#include <cuda_fp16.h>
#include <math.h>
#include <stdint.h>

#define S_LEN   2048
#define BATCH   2
#define NH      16
#define HID     2048
#define QL      1536
#define KVL     512
#define DR      64
#define DN      128
#define DVV     128
#define DQK     192
#define NTOK    (BATCH * S_LEN)     // 4096
#define CKV_W   (KVL + DR)          // 576

// ---------------- scratch (static device globals, fp16) ----------------------
__device__ __half g_qa [NTOK * QL];
__device__ __half g_q  [NTOK * NH * DQK];
__device__ __half g_ckv[NTOK * CKV_W];
__device__ __half g_ckn[NTOK * KVL];
__device__ __half g_kv [NTOK * NH * 256];
__device__ __half g_kr [NTOK * DR];
__device__ __half g_ao [NTOK * NH * DVV];
__device__ __half g_hid [NTOK * HID];
// transposed fp16 weights, [N][K] K-major
__device__ __half g_wqaT [QL * HID];
__device__ __half g_wqbT [NH * DQK * QL];
__device__ __half g_wkvaT[768 * HID];          // 576 padded to 768 rows
__device__ __half g_wkvbT[NH * 256 * KVL];
__device__ __half g_woT  [HID * HID];

// ---------------- helpers -----------------------------------------------------
__device__ __forceinline__ uint32_t ldh2(const __half* p) {
    return *reinterpret_cast<const uint32_t*>(p);
}
__device__ __forceinline__ void sth2(__half* p, uint32_t v) {
    *reinterpret_cast<uint32_t*>(p) = v;
}
__device__ __forceinline__ uint32_t pkh2(float a, float b) {
    __half2 h = __floats2half2_rn(a, b);
    return *reinterpret_cast<uint32_t*>(&h);
}

__device__ __forceinline__ void mma_f16(float (&c)[4],
    uint32_t a0, uint32_t a1, uint32_t a2, uint32_t a3,
    uint32_t b0, uint32_t b1)
{
    asm volatile(
        "mma.sync.aligned.m16n8k16.row.col.f32.f16.f16.f32 "
        "{%0,%1,%2,%3},{%4,%5,%6,%7},{%8,%9},{%0,%1,%2,%3};"
        : "+f"(c[0]), "+f"(c[1]), "+f"(c[2]), "+f"(c[3])
        : "r"(a0), "r"(a1), "r"(a2), "r"(a3), "r"(b0), "r"(b1));
}

__device__ __forceinline__ uint32_t smem_u32(const void* p) {
    uint32_t a;
    asm("{ .reg .u64 t; cvta.to.shared.u64 t, %1; cvt.u32.u64 %0, t; }"
        : "=r"(a) : "l"(p));
    return a;
}
__device__ __forceinline__ void cp16u(uint32_t dst, const void* src) {
    asm volatile("cp.async.cg.shared.global [%0], [%1], 16;\n"
                 :: "r"(dst), "l"(src));
}
__device__ __forceinline__ void cp_commit() { asm volatile("cp.async.commit_group;\n"); }
__device__ __forceinline__ void cp_wait0()  { asm volatile("cp.async.wait_group 0;\n" ::: "memory"); }
__device__ __forceinline__ void cp_wait1()  { asm volatile("cp.async.wait_group 1;\n" ::: "memory"); }

// ---------------- fp16 GEMM: C[M,N] = A[M,K] @ Bt[N,K]^T ----------------------
// 128x128 block, BK=32 halves, 256 threads, warp grid 2x4, warp tile 64x32.
#define GST 40

__global__ __launch_bounds__(256) void gemm_f16k(
    const __half* __restrict__ A, const __half* __restrict__ Bt,
    void* __restrict__ Cv, int M, int N, int K, int fp32_out)
{
    __shared__ __half As[2][128 * GST];
    __shared__ __half Bs[2][128 * GST];
    const int tid = threadIdx.x;
    const int wid = tid >> 5, lane = tid & 31;
    const int wm = wid >> 2, wn = wid & 3;
    const int row0 = blockIdx.y << 7;
    const int col0 = blockIdx.x << 7;
    const int tg = lane & 3, gp = lane >> 2;
    const int NS = K >> 5;

    const uint32_t asb[2] = {smem_u32(&As[0][0]), smem_u32(&As[1][0])};
    const uint32_t bsb[2] = {smem_u32(&Bs[0][0]), smem_u32(&Bs[1][0])};

    const int sr0 = tid >> 2, sc0 = (tid & 3) << 3;
    const int sr1 = (tid + 256) >> 2, sc1 = ((tid + 256) & 3) << 3;

    float acc[4][4][4];
    #pragma unroll
    for (int mt = 0; mt < 4; mt++)
        #pragma unroll
        for (int nt = 0; nt < 4; nt++)
            #pragma unroll
            for (int r = 0; r < 4; r++) acc[mt][nt][r] = 0.f;

    cp16u(asb[0] + sr0 * (GST * 2) + sc0 * 2, A  + (size_t)(row0 + sr0) * K + sc0);
    cp16u(asb[0] + sr1 * (GST * 2) + sc1 * 2, A  + (size_t)(row0 + sr1) * K + sc1);
    cp16u(bsb[0] + sr0 * (GST * 2) + sc0 * 2, Bt + (size_t)(col0 + sr0) * K + sc0);
    cp16u(bsb[0] + sr1 * (GST * 2) + sc1 * 2, Bt + (size_t)(col0 + sr1) * K + sc1);
    cp_commit();

    for (int s = 0; s < NS; s++) {
        const int b = s & 1;
        if (s + 1 < NS) {
            const int nb = b ^ 1;
            const int k0 = (s + 1) << 5;
            cp16u(asb[nb] + sr0 * (GST * 2) + sc0 * 2, A  + (size_t)(row0 + sr0) * K + k0 + sc0);
            cp16u(asb[nb] + sr1 * (GST * 2) + sc1 * 2, A  + (size_t)(row0 + sr1) * K + k0 + sc1);
            cp16u(bsb[nb] + sr0 * (GST * 2) + sc0 * 2, Bt + (size_t)(col0 + sr0) * K + k0 + sc0);
            cp16u(bsb[nb] + sr1 * (GST * 2) + sc1 * 2, Bt + (size_t)(col0 + sr1) * K + k0 + sc1);
            cp_commit();
            cp_wait1();
        } else {
            cp_wait0();
        }
        __syncthreads();

        const __half* as = As[b];
        const __half* bs = Bs[b];
        #pragma unroll
        for (int ks = 0; ks < 2; ks++) {
            const int kk = ks << 4;
            uint32_t a[4][4];
            #pragma unroll
            for (int mt = 0; mt < 4; mt++) {
                int ra = (wm << 6) + (mt << 4) + gp;
                a[mt][0] = ldh2(&as[ra * GST + kk + 2 * tg]);
                a[mt][1] = ldh2(&as[(ra + 8) * GST + kk + 2 * tg]);
                a[mt][2] = ldh2(&as[ra * GST + kk + 2 * tg + 8]);
                a[mt][3] = ldh2(&as[(ra + 8) * GST + kk + 2 * tg + 8]);
            }
            #pragma unroll
            for (int nt = 0; nt < 4; nt++) {
                int nb2 = (wn << 5) + (nt << 3) + gp;
                uint32_t b0 = ldh2(&bs[nb2 * GST + kk + 2 * tg]);
                uint32_t b1 = ldh2(&bs[nb2 * GST + kk + 2 * tg + 8]);
                #pragma unroll
                for (int mt = 0; mt < 4; mt++)
                    mma_f16(acc[mt][nt], a[mt][0], a[mt][1], a[mt][2], a[mt][3], b0, b1);
            }
        }
        __syncthreads();
    }

    #pragma unroll
    for (int mt = 0; mt < 4; mt++) {
        int row = row0 + (wm << 6) + (mt << 4) + gp;
        #pragma unroll
        for (int nt = 0; nt < 4; nt++) {
            int col = col0 + (wn << 5) + (nt << 3) + (tg << 1);
            if (col < N) {
                if (fp32_out) {
                    float* C = (float*)Cv;
                    *reinterpret_cast<float2*>(&C[(size_t)row * N + col]) =
                        make_float2(acc[mt][nt][0], acc[mt][nt][1]);
                    *reinterpret_cast<float2*>(&C[(size_t)(row + 8) * N + col]) =
                        make_float2(acc[mt][nt][2], acc[mt][nt][3]);
                } else {
                    __half* C = (__half*)Cv;
                    sth2(&C[(size_t)row * N + col], pkh2(acc[mt][nt][0], acc[mt][nt][1]));
                    sth2(&C[(size_t)(row + 8) * N + col], pkh2(acc[mt][nt][2], acc[mt][nt][3]));
                }
            }
        }
    }
}

// ---------------- hidden -> fp16 ----------------------------------------------
__global__ void round_h(const float* __restrict__ in, __half* __restrict__ out, int n4)
{
    int i = blockIdx.x * blockDim.x + threadIdx.x;
    if (i < n4) {
        float4 v = reinterpret_cast<const float4*>(in)[i];
        uint32_t lo = pkh2(v.x, v.y), hi = pkh2(v.z, v.w);
        reinterpret_cast<uint2*>(out)[i] = make_uint2(lo, hi);
    }
}

// ---------------- weight transpose -> fp16 [N][K] ------------------------------
struct TParams { const float* src; __half* dst; int R, C, Cpad; };
struct TAll { TParams p[5]; };

__global__ void transpose_h(TAll t)
{
    const TParams pp = t.p[blockIdx.z];
    const int cx = blockIdx.x << 5, ry = blockIdx.y << 5;
    if (cx >= pp.Cpad || ry >= pp.R) return;
    __shared__ float tile[32][33];
    #pragma unroll
    for (int i = 0; i < 4; i++) {
        int r = ry + threadIdx.y + (i << 3);
        int c = cx + threadIdx.x;
        float v = 0.f;
        if (r < pp.R && c < pp.C) v = pp.src[(size_t)r * pp.C + c];
        tile[threadIdx.y + (i << 3)][threadIdx.x] = v;
    }
    __syncthreads();
    #pragma unroll
    for (int i = 0; i < 4; i++) {
        int outr = cx + threadIdx.y + (i << 3);
        int outc = ry + threadIdx.x;
        if (outr < pp.Cpad && outc < pp.R)
            pp.dst[(size_t)outr * pp.R + outc] = __float2half_rn(tile[threadIdx.x][threadIdx.y + (i << 3)]);
    }
}

// ---------------- RMSNorm (fp16 in/out, fp32 math) -----------------------------
__global__ __launch_bounds__(256) void rmsnorm_h(
    const __half* __restrict__ in, const float* __restrict__ w,
    __half* __restrict__ out, int in_stride, int out_stride, int n)
{
    const int row = blockIdx.x;
    const __half* x = in + (size_t)row * in_stride;
    float ss = 0.f;
    for (int j = threadIdx.x; j < n; j += 256) { float v = __half2float(x[j]); ss += v * v; }
    __shared__ float red[8];
    #pragma unroll
    for (int off = 16; off; off >>= 1) ss += __shfl_xor_sync(~0u, ss, off);
    if ((threadIdx.x & 31) == 0) red[threadIdx.x >> 5] = ss;
    __syncthreads();
    if (threadIdx.x == 0) {
        float t = 0.f;
        #pragma unroll
        for (int i = 0; i < 8; i++) t += red[i];
        red[0] = rsqrtf(t / n + 1e-6f);
    }
    __syncthreads();
    const float r = red[0];
    __half* y = out + (size_t)row * out_stride;
    for (int j = threadIdx.x; j < n; j += 256)
        y[j] = __float2half_rn(w[j] * __half2float(x[j]) * r);
}

// ---------------- RoPE (fp16) ---------------------------------------------------
__global__ void rope_q_h(__half* __restrict__ q,
                         const float* __restrict__ cosb,
                         const float* __restrict__ sinb)
{
    const int t = blockIdx.x;
    const int h = threadIdx.x >> 5;
    const int i = threadIdx.x & 31;
    const int s = t & (S_LEN - 1);
    const float cv = cosb[s * DR + 2 * i];
    const float sv = sinb[s * DR + 2 * i];
    __half* p = q + (size_t)t * NH * DQK + h * DQK + DN + 2 * i;
    const float xr = __half2float(p[0]), xi = __half2float(p[1]);
    sth2(p, pkh2(xr * cv - xi * sv, xr * sv + xi * cv));
}

__global__ void rope_k_h(const __half* __restrict__ ckv,
                         const float* __restrict__ cosb,
                         const float* __restrict__ sinb,
                         __half* __restrict__ kr)
{
    const int t = blockIdx.x;
    const int i = threadIdx.x;
    const int s = t & (S_LEN - 1);
    const float cv = cosb[s * DR + 2 * i];
    const float sv = sinb[s * DR + 2 * i];
    const float xr = __half2float(ckv[(size_t)t * CKV_W + KVL + 2 * i]);
    const float xi = __half2float(ckv[(size_t)t * CKV_W + KVL + 2 * i + 1]);
    sth2(&kr[t * DR + 2 * i], pkh2(xr * cv - xi * sv, xr * sv + xi * cv));
}

// ---------------- Flash attention, fp16 mma ------------------------------------
// BM=128 (8 warps x 16 rows), BN=64, D=192. grid (16, 32), 256 threads.
#define QST 200
#define VST 72
#define PST 72
#define SH_Q 0
#define SH_K (SH_Q + 128 * QST)
#define SH_V (SH_K + 64 * QST)
#define SH_P (SH_V + 128 * VST)
#define ATTN_SMEM_BYTES ((SH_P + 128 * PST) * 2)

__global__ __launch_bounds__(256) void attn_f16(
    const __half* __restrict__ q, const __half* __restrict__ kv,
    const __half* __restrict__ kr, __half* __restrict__ ao)
{
    extern __shared__ __half sh[];
    __half* Qs = sh + SH_Q;
    __half* Ks = sh + SH_K;
    __half* Vs = sh + SH_V;
    __half* Ps = sh + SH_P;

    const int tid = threadIdx.x;
    const int wid = tid >> 5, lane = tid & 31;
    const int tg = lane & 3, gp = lane >> 2;
    const int r0 = wid << 4;
    const int bh = blockIdx.y;
    const int b = bh >> 4, h = bh & 15;
    const int q0 = blockIdx.x << 7;
    const size_t tokbase = (size_t)b * S_LEN;
    const float scale = rsqrtf((float)DQK);

    for (int f = tid; f < 128 * 24; f += 256) {
        int r = f / 24, c = (f % 24) << 3;
        *reinterpret_cast<float4*>(&Qs[r * QST + c]) =
            *reinterpret_cast<const float4*>(
                &q[(tokbase + q0 + r) * (NH * DQK) + h * DQK + c]);
    }

    float m_[2] = {-1e30f, -1e30f};
    float l_[2] = {0.f, 0.f};
    float o[16][4];
    #pragma unroll
    for (int nt = 0; nt < 16; nt++)
        #pragma unroll
        for (int r = 0; r < 4; r++) o[nt][r] = 0.f;

    for (int kb = 0; kb < S_LEN; kb += 64) {
        __syncthreads();
        for (int f = tid; f < 64 * 24; f += 256) {
            int r = f / 24, c = (f % 24) << 3;
            float4 v;
            if (c < DN)
                v = *reinterpret_cast<const float4*>(
                    &kv[(tokbase + kb + r) * (NH * 256) + h * 256 + c]);
            else
                v = *reinterpret_cast<const float4*>(
                    &kr[(tokbase + kb + r) * DR + (c - DN)]);
            *reinterpret_cast<float4*>(&Ks[r * QST + c]) = v;
        }
        for (int f = tid; f < 64 * 16; f += 256) {
            int r = f & 63, dg = (f >> 6) << 3;
            float4 v = *reinterpret_cast<const float4*>(
                &kv[(tokbase + kb + r) * (NH * 256) + h * 256 + DN + dg]);
            const __half* hv = reinterpret_cast<const __half*>(&v);
            #pragma unroll
            for (int i = 0; i < 8; i++) Vs[(dg + i) * VST + r] = hv[i];
        }
        __syncthreads();

        float s[8][4];
        #pragma unroll
        for (int nt = 0; nt < 8; nt++)
            #pragma unroll
            for (int r = 0; r < 4; r++) s[nt][r] = 0.f;

        #pragma unroll
        for (int ks = 0; ks < 12; ks++) {
            const int kk = ks << 4;
            const int ra = r0 + gp;
            uint32_t a0 = ldh2(&Qs[ra * QST + kk + 2 * tg]);
            uint32_t a1 = ldh2(&Qs[(ra + 8) * QST + kk + 2 * tg]);
            uint32_t a2 = ldh2(&Qs[ra * QST + kk + 2 * tg + 8]);
            uint32_t a3 = ldh2(&Qs[(ra + 8) * QST + kk + 2 * tg + 8]);
            #pragma unroll
            for (int nt = 0; nt < 8; nt++) {
                int nb = (nt << 3) + gp;
                uint32_t b0 = ldh2(&Ks[nb * QST + kk + 2 * tg]);
                uint32_t b1 = ldh2(&Ks[nb * QST + kk + 2 * tg + 8]);
                mma_f16(s[nt], a0, a1, a2, a3, b0, b1);
            }
        }

        #pragma unroll
        for (int hr = 0; hr < 2; hr++) {
            float mx = -1e30f;
            #pragma unroll
            for (int nt = 0; nt < 8; nt++) {
                s[nt][2 * hr]     *= scale;
                s[nt][2 * hr + 1] *= scale;
                mx = fmaxf(mx, fmaxf(s[nt][2 * hr], s[nt][2 * hr + 1]));
            }
            mx = fmaxf(mx, __shfl_xor_sync(~0u, mx, 1));
            mx = fmaxf(mx, __shfl_xor_sync(~0u, mx, 2));
            float nm = fmaxf(m_[hr], mx);
            float alpha = __expf(m_[hr] - nm);
            float ls = 0.f;
            #pragma unroll
            for (int nt = 0; nt < 8; nt++) {
                float p0 = __expf(s[nt][2 * hr] - nm);
                float p1 = __expf(s[nt][2 * hr + 1] - nm);
                s[nt][2 * hr] = p0; s[nt][2 * hr + 1] = p1;
                ls += p0 + p1;
            }
            ls += __shfl_xor_sync(~0u, ls, 1);
            ls += __shfl_xor_sync(~0u, ls, 2);
            l_[hr] = l_[hr] * alpha + ls;
            m_[hr] = nm;
            #pragma unroll
            for (int nt = 0; nt < 16; nt++) {
                o[nt][2 * hr]     *= alpha;
                o[nt][2 * hr + 1] *= alpha;
            }
            int pr = r0 + gp + (hr << 3);
            #pragma unroll
            for (int nt = 0; nt < 8; nt++)
                sth2(&Ps[pr * PST + (nt << 3) + (tg << 1)],
                     pkh2(s[nt][2 * hr], s[nt][2 * hr + 1]));
        }
        __syncwarp();

        #pragma unroll
        for (int ks = 0; ks < 4; ks++) {
            const int kk = ks << 4;
            const int ra = r0 + gp;
            uint32_t a0 = ldh2(&Ps[ra * PST + kk + 2 * tg]);
            uint32_t a1 = ldh2(&Ps[(ra + 8) * PST + kk + 2 * tg]);
            uint32_t a2 = ldh2(&Ps[ra * PST + kk + 2 * tg + 8]);
            uint32_t a3 = ldh2(&Ps[(ra + 8) * PST + kk + 2 * tg + 8]);
            #pragma unroll
            for (int nt = 0; nt < 16; nt++) {
                int nb = (nt << 3) + gp;
                uint32_t b0 = ldh2(&Vs[nb * VST + kk + 2 * tg]);
                uint32_t b1 = ldh2(&Vs[nb * VST + kk + 2 * tg + 8]);
                mma_f16(o[nt], a0, a1, a2, a3, b0, b1);
            }
        }
    }

    float inv0 = 1.0f / l_[0], inv1 = 1.0f / l_[1];
    size_t rlo = (tokbase + q0 + r0 + gp) * (size_t)(NH * DVV) + h * DVV;
    size_t rhi = (tokbase + q0 + r0 + gp + 8) * (size_t)(NH * DVV) + h * DVV;
    #pragma unroll
    for (int nt = 0; nt < 16; nt++) {
        int col = (nt << 3) + (tg << 1);
        sth2(&ao[rlo + col], pkh2(o[nt][0] * inv0, o[nt][1] * inv0));
        sth2(&ao[rhi + col], pkh2(o[nt][2] * inv1, o[nt][3] * inv1));
    }
}

// ---------------- launch --------------------------------------------------------
extern "C" void kernel_launch(void* const* d_in, const int* in_sizes, int n_in,
                              void* d_out, int out_size)
{
    const float* hidden  = (const float*)d_in[0];
    const float* cosb    = (const float*)d_in[1];
    const float* sinb    = (const float*)d_in[2];
    const float* q_a_w   = (const float*)d_in[3];
    const float* q_a_ln  = (const float*)d_in[4];
    const float* q_b_w   = (const float*)d_in[5];
    const float* kv_a_w  = (const float*)d_in[6];
    const float* kv_a_ln = (const float*)d_in[7];
    const float* kv_b_w  = (const float*)d_in[8];
    const float* o_w     = (const float*)d_in[9];
    float* out = (float*)d_out;

    __half *qa, *qq, *ckv, *ckn, *kvf, *kr, *ao, *hid;
    __half *wqaT, *wqbT, *wkvaT, *wkvbT, *woT;
    cudaGetSymbolAddress((void**)&qa,    g_qa);
    cudaGetSymbolAddress((void**)&qq,    g_q);
    cudaGetSymbolAddress((void**)&ckv,   g_ckv);
    cudaGetSymbolAddress((void**)&ckn,   g_ckn);
    cudaGetSymbolAddress((void**)&kvf,   g_kv);
    cudaGetSymbolAddress((void**)&kr,    g_kr);
    cudaGetSymbolAddress((void**)&ao,    g_ao);
    cudaGetSymbolAddress((void**)&hid,   g_hid);
    cudaGetSymbolAddress((void**)&wqaT,  g_wqaT);
    cudaGetSymbolAddress((void**)&wqbT,  g_wqbT);
    cudaGetSymbolAddress((void**)&wkvaT, g_wkvaT);
    cudaGetSymbolAddress((void**)&wkvbT, g_wkvbT);
    cudaGetSymbolAddress((void**)&woT,   g_woT);

    cudaFuncSetAttribute(attn_f16,
        cudaFuncAttributeMaxDynamicSharedMemorySize, ATTN_SMEM_BYTES);

    // [0] hidden -> fp16
    round_h<<<(NTOK * HID / 4 + 255) / 256, 256>>>(hidden, hid, NTOK * HID / 4);

    // [1] transpose weights -> fp16 [N][K]
    TAll ta;
    ta.p[0] = {q_a_w,  wqaT,  HID, QL,       QL};
    ta.p[1] = {q_b_w,  wqbT,  QL,  NH * DQK, NH * DQK};
    ta.p[2] = {kv_a_w, wkvaT, HID, CKV_W,    768};
    ta.p[3] = {kv_b_w, wkvbT, KVL, NH * 256, NH * 256};
    ta.p[4] = {o_w,    woT,   HID, HID,      HID};
    transpose_h<<<dim3(128, 64, 5), dim3(32, 8)>>>(ta);

    // [2] q_a = hid @ q_a_w
    gemm_f16k<<<dim3(QL / 128, NTOK / 128), 256>>>(hid, wqaT, qa, NTOK, QL, HID, 0);
    // [3] ckv = hid @ kv_a_w
    gemm_f16k<<<dim3(5, NTOK / 128), 256>>>(hid, wkvaT, ckv, NTOK, CKV_W, HID, 0);
    // [4] rmsnorm q_a (in place)
    rmsnorm_h<<<NTOK, 256>>>(qa, q_a_ln, qa, QL, QL, QL);
    // [5] q = qa @ q_b_w
    gemm_f16k<<<dim3(NH * DQK / 128, NTOK / 128), 256>>>(qa, wqbT, qq, NTOK, NH * DQK, QL, 0);
    // [6] rmsnorm ckv -> ckn
    rmsnorm_h<<<NTOK, 256>>>(ckv, kv_a_ln, ckn, CKV_W, KVL, KVL);
    // [7] kv = ckn @ kv_b_w
    gemm_f16k<<<dim3(NH * 256 / 128, NTOK / 128), 256>>>(ckn, wkvbT, kvf, NTOK, NH * 256, KVL, 0);
    // [8] rope q (in place)
    rope_q_h<<<NTOK, NH * 32>>>(qq, cosb, sinb);
    // [9] rope k_rope -> kr
    rope_k_h<<<NTOK, 32>>>(ckv, cosb, sinb, kr);
    // [10] attention
    attn_f16<<<dim3(S_LEN / 128, BATCH * NH), 256, ATTN_SMEM_BYTES>>>(qq, kvf, kr, ao);
    // [11] out = ao @ o_w (fp32 out)
    gemm_f16k<<<dim3(HID / 128, NTOK / 128), 256>>>(ao, woT, out, NTOK, HID, HID, 1);
}

// round 10
// speedup vs baseline: 8.3042x; 1.1020x over previous
#include <cuda_runtime.h>
#include <cuda_fp16.h>
#include <math.h>
#include <stdint.h>

#define S_LEN   2048
#define BATCH   2
#define NH      16
#define HID     2048
#define QL      1536
#define KVL     512
#define DR      64
#define DN      128
#define DVV     128
#define DQK     192
#define NTOK    (BATCH * S_LEN)     // 4096
#define CKV_W   (KVL + DR)          // 576

// ---------------- scratch (static device globals, fp16) ----------------------
__device__ __half g_qa [NTOK * QL];
__device__ __half g_q  [NTOK * NH * DQK];
__device__ __half g_ckv[NTOK * CKV_W];
__device__ __half g_ckn[NTOK * KVL];
__device__ __half g_kv [NTOK * NH * 256];
__device__ __half g_kr [NTOK * DR];
__device__ __half g_ao [NTOK * NH * DVV];
__device__ __half g_hid [NTOK * HID];
__device__ __half g_wqaT [QL * HID];
__device__ __half g_wqbT [NH * DQK * QL];
__device__ __half g_wkvaT[768 * HID];          // 576 padded to 768 rows
__device__ __half g_wkvbT[NH * 256 * KVL];
__device__ __half g_woT  [HID * HID];

// ---------------- helpers -----------------------------------------------------
__device__ __forceinline__ void sth2(__half* p, uint32_t v) {
    *reinterpret_cast<uint32_t*>(p) = v;
}
__device__ __forceinline__ uint32_t pkh2(float a, float b) {
    __half2 h = __floats2half2_rn(a, b);
    return *reinterpret_cast<uint32_t*>(&h);
}
__device__ __forceinline__ void mma_f16(float (&c)[4],
    uint32_t a0, uint32_t a1, uint32_t a2, uint32_t a3,
    uint32_t b0, uint32_t b1)
{
    asm volatile(
        "mma.sync.aligned.m16n8k16.row.col.f32.f16.f16.f32 "
        "{%0,%1,%2,%3},{%4,%5,%6,%7},{%8,%9},{%0,%1,%2,%3};"
        : "+f"(c[0]), "+f"(c[1]), "+f"(c[2]), "+f"(c[3])
        : "r"(a0), "r"(a1), "r"(a2), "r"(a3), "r"(b0), "r"(b1));
}
__device__ __forceinline__ void ldmx4(uint32_t (&r)[4], uint32_t addr) {
    asm volatile("ldmatrix.sync.aligned.m8n8.x4.shared.b16 {%0,%1,%2,%3}, [%4];"
        : "=r"(r[0]), "=r"(r[1]), "=r"(r[2]), "=r"(r[3]) : "r"(addr));
}
__device__ __forceinline__ uint32_t smem_u32(const void* p) {
    uint32_t a;
    asm("{ .reg .u64 t; cvta.to.shared.u64 t, %1; cvt.u32.u64 %0, t; }"
        : "=r"(a) : "l"(p));
    return a;
}
__device__ __forceinline__ void cp16u(uint32_t dst, const void* src) {
    asm volatile("cp.async.cg.shared.global [%0], [%1], 16;\n"
                 :: "r"(dst), "l"(src));
}
__device__ __forceinline__ void cp_commit() { asm volatile("cp.async.commit_group;\n"); }
__device__ __forceinline__ void cp_wait0()  { asm volatile("cp.async.wait_group 0;\n" ::: "memory"); }
__device__ __forceinline__ void cp_wait1()  { asm volatile("cp.async.wait_group 1;\n" ::: "memory"); }

// ---------------- fp16 GEMM: C[M,N] = A[M,K] @ Bt[N,K]^T ----------------------
// 128x128 block, BK=64 halves, 2-stage cp.async, ldmatrix fragments.
// 256 threads, warp grid 2(M)x4(N), warp tile 64x32.
#define GST 72                         // stride in halves; 144B row delta -> conflict-free
#define GEMM_SMEM (4 * 128 * GST * 2)  // 2 stages x (A+B) x 128 rows = 73728 B

__global__ __launch_bounds__(256, 2) void gemm_f16k(
    const __half* __restrict__ A, const __half* __restrict__ Bt,
    void* __restrict__ Cv, int M, int N, int K, int fp32_out)
{
    extern __shared__ __half gsm[];
    const int tid = threadIdx.x;
    const int wid = tid >> 5, lane = tid & 31;
    const int wm = wid >> 2, wn = wid & 3;
    const int row0 = blockIdx.y << 7;
    const int col0 = blockIdx.x << 7;
    const int NS = K >> 6;

    const uint32_t smb = smem_u32(gsm);
    // half offsets: stage s: A at s*2*128*GST, B at that + 128*GST
    const uint32_t stA[2] = {smb,                     smb + 2u * 128 * GST * 2};
    const uint32_t stB[2] = {smb + 128u * GST * 2,    smb + 3u * 128 * GST * 2};

    // staging coords: 8 chunks (16B) per row, 1024 chunks, 4 per thread
    // chunk c: row = c>>3, kcol = (c&7)*8 halves
    // ldmatrix lane geometry
    const int lmr = lane & 15;
    const int lmk = (lane >> 4) << 3;
    const uint32_t a_off = ((uint32_t)((wm << 6) + lmr) * GST + lmk) * 2;
    const uint32_t b_off = ((uint32_t)((wn << 5) + lmr) * GST + lmk) * 2;

    float acc[4][4][4];
    #pragma unroll
    for (int mt = 0; mt < 4; mt++)
        #pragma unroll
        for (int nt = 0; nt < 4; nt++)
            #pragma unroll
            for (int r = 0; r < 4; r++) acc[mt][nt][r] = 0.f;

    // stage slab 0 -> stage 0
    #pragma unroll
    for (int i = 0; i < 4; i++) {
        int c = tid + (i << 8);
        int r = c >> 3, kc = (c & 7) << 3;
        cp16u(stA[0] + ((uint32_t)r * GST + kc) * 2, A  + (size_t)(row0 + r) * K + kc);
        cp16u(stB[0] + ((uint32_t)r * GST + kc) * 2, Bt + (size_t)(col0 + r) * K + kc);
    }
    cp_commit();

    for (int s = 0; s < NS; s++) {
        const int b = s & 1;
        if (s + 1 < NS) {
            const int nb = b ^ 1;
            const int k0 = (s + 1) << 6;
            #pragma unroll
            for (int i = 0; i < 4; i++) {
                int c = tid + (i << 8);
                int r = c >> 3, kc = (c & 7) << 3;
                cp16u(stA[nb] + ((uint32_t)r * GST + kc) * 2, A  + (size_t)(row0 + r) * K + k0 + kc);
                cp16u(stB[nb] + ((uint32_t)r * GST + kc) * 2, Bt + (size_t)(col0 + r) * K + k0 + kc);
            }
            cp_commit();
            cp_wait1();
        } else {
            cp_wait0();
        }
        __syncthreads();

        const uint32_t ab = stA[b] + a_off;
        const uint32_t bb = stB[b] + b_off;
        #pragma unroll
        for (int ks = 0; ks < 4; ks++) {
            const uint32_t kby = (uint32_t)(ks << 4) * 2;   // kk halves -> bytes
            uint32_t af[4][4];
            #pragma unroll
            for (int mt = 0; mt < 4; mt++)
                ldmx4(af[mt], ab + (uint32_t)(mt << 4) * GST * 2 + kby);
            #pragma unroll
            for (int ntp = 0; ntp < 2; ntp++) {
                uint32_t bf[4];
                ldmx4(bf, bb + (uint32_t)(ntp << 4) * GST * 2 + kby);
                #pragma unroll
                for (int mt = 0; mt < 4; mt++) {
                    mma_f16(acc[mt][2 * ntp],     af[mt][0], af[mt][1], af[mt][2], af[mt][3], bf[0], bf[2]);
                    mma_f16(acc[mt][2 * ntp + 1], af[mt][0], af[mt][1], af[mt][2], af[mt][3], bf[1], bf[3]);
                }
            }
        }
        __syncthreads();
    }

    const int tg = lane & 3, gp = lane >> 2;
    #pragma unroll
    for (int mt = 0; mt < 4; mt++) {
        int row = row0 + (wm << 6) + (mt << 4) + gp;
        #pragma unroll
        for (int nt = 0; nt < 4; nt++) {
            int col = col0 + (wn << 5) + (nt << 3) + (tg << 1);
            if (col < N) {
                if (fp32_out) {
                    float* C = (float*)Cv;
                    *reinterpret_cast<float2*>(&C[(size_t)row * N + col]) =
                        make_float2(acc[mt][nt][0], acc[mt][nt][1]);
                    *reinterpret_cast<float2*>(&C[(size_t)(row + 8) * N + col]) =
                        make_float2(acc[mt][nt][2], acc[mt][nt][3]);
                } else {
                    __half* C = (__half*)Cv;
                    sth2(&C[(size_t)row * N + col], pkh2(acc[mt][nt][0], acc[mt][nt][1]));
                    sth2(&C[(size_t)(row + 8) * N + col], pkh2(acc[mt][nt][2], acc[mt][nt][3]));
                }
            }
        }
    }
}

// ---------------- hidden -> fp16 ----------------------------------------------
__global__ void round_h(const float* __restrict__ in, __half* __restrict__ out, int n4)
{
    int i = blockIdx.x * blockDim.x + threadIdx.x;
    if (i < n4) {
        float4 v = reinterpret_cast<const float4*>(in)[i];
        reinterpret_cast<uint2*>(out)[i] = make_uint2(pkh2(v.x, v.y), pkh2(v.z, v.w));
    }
}

// ---------------- weight transpose -> fp16 [N][K] ------------------------------
struct TParams { const float* src; __half* dst; int R, C, Cpad; };
struct TAll { TParams p[5]; };

__global__ void transpose_h(TAll t)
{
    const TParams pp = t.p[blockIdx.z];
    const int cx = blockIdx.x << 5, ry = blockIdx.y << 5;
    if (cx >= pp.Cpad || ry >= pp.R) return;
    __shared__ float tile[32][33];
    #pragma unroll
    for (int i = 0; i < 4; i++) {
        int r = ry + threadIdx.y + (i << 3);
        int c = cx + threadIdx.x;
        float v = 0.f;
        if (r < pp.R && c < pp.C) v = pp.src[(size_t)r * pp.C + c];
        tile[threadIdx.y + (i << 3)][threadIdx.x] = v;
    }
    __syncthreads();
    #pragma unroll
    for (int i = 0; i < 4; i++) {
        int outr = cx + threadIdx.y + (i << 3);
        int outc = ry + threadIdx.x;
        if (outr < pp.Cpad && outc < pp.R)
            pp.dst[(size_t)outr * pp.R + outc] = __float2half_rn(tile[threadIdx.x][threadIdx.y + (i << 3)]);
    }
}

// ---------------- RMSNorm (fp16 in/out, fp32 math) -----------------------------
__global__ __launch_bounds__(256) void rmsnorm_h(
    const __half* __restrict__ in, const float* __restrict__ w,
    __half* __restrict__ out, int in_stride, int out_stride, int n)
{
    const int row = blockIdx.x;
    const __half* x = in + (size_t)row * in_stride;
    float ss = 0.f;
    for (int j = threadIdx.x; j < n; j += 256) { float v = __half2float(x[j]); ss += v * v; }
    __shared__ float red[8];
    #pragma unroll
    for (int off = 16; off; off >>= 1) ss += __shfl_xor_sync(~0u, ss, off);
    if ((threadIdx.x & 31) == 0) red[threadIdx.x >> 5] = ss;
    __syncthreads();
    if (threadIdx.x == 0) {
        float t = 0.f;
        #pragma unroll
        for (int i = 0; i < 8; i++) t += red[i];
        red[0] = rsqrtf(t / n + 1e-6f);
    }
    __syncthreads();
    const float r = red[0];
    __half* y = out + (size_t)row * out_stride;
    for (int j = threadIdx.x; j < n; j += 256)
        y[j] = __float2half_rn(w[j] * __half2float(x[j]) * r);
}

// ---------------- RoPE (fp16) ---------------------------------------------------
__global__ void rope_q_h(__half* __restrict__ q,
                         const float* __restrict__ cosb,
                         const float* __restrict__ sinb)
{
    const int t = blockIdx.x;
    const int h = threadIdx.x >> 5;
    const int i = threadIdx.x & 31;
    const int s = t & (S_LEN - 1);
    const float cv = cosb[s * DR + 2 * i];
    const float sv = sinb[s * DR + 2 * i];
    __half* p = q + (size_t)t * NH * DQK + h * DQK + DN + 2 * i;
    const float xr = __half2float(p[0]), xi = __half2float(p[1]);
    sth2(p, pkh2(xr * cv - xi * sv, xr * sv + xi * cv));
}

__global__ void rope_k_h(const __half* __restrict__ ckv,
                         const float* __restrict__ cosb,
                         const float* __restrict__ sinb,
                         __half* __restrict__ kr)
{
    const int t = blockIdx.x;
    const int i = threadIdx.x;
    const int s = t & (S_LEN - 1);
    const float cv = cosb[s * DR + 2 * i];
    const float sv = sinb[s * DR + 2 * i];
    const float xr = __half2float(ckv[(size_t)t * CKV_W + KVL + 2 * i]);
    const float xi = __half2float(ckv[(size_t)t * CKV_W + KVL + 2 * i + 1]);
    sth2(&kr[t * DR + 2 * i], pkh2(xr * cv - xi * sv, xr * sv + xi * cv));
}

// ---------------- Flash attention, fp16 mma + ldmatrix --------------------------
// BM=128 (8 warps x 16 rows), BN=64, D=192. grid (16, 32), 256 threads.
#define QST 200
#define VST 72
#define PST 72
#define SH_Q 0
#define SH_K (SH_Q + 128 * QST)
#define SH_V (SH_K + 64 * QST)
#define SH_P (SH_V + 128 * VST)
#define ATTN_SMEM_BYTES ((SH_P + 128 * PST) * 2)

__global__ __launch_bounds__(256) void attn_f16(
    const __half* __restrict__ q, const __half* __restrict__ kv,
    const __half* __restrict__ kr, __half* __restrict__ ao)
{
    extern __shared__ __half sh[];
    __half* Qs = sh + SH_Q;
    __half* Ks = sh + SH_K;
    __half* Vs = sh + SH_V;
    __half* Ps = sh + SH_P;

    const int tid = threadIdx.x;
    const int wid = tid >> 5, lane = tid & 31;
    const int tg = lane & 3, gp = lane >> 2;
    const int r0 = wid << 4;
    const int bh = blockIdx.y;
    const int b = bh >> 4, h = bh & 15;
    const int q0 = blockIdx.x << 7;
    const size_t tokbase = (size_t)b * S_LEN;
    const float scale = rsqrtf((float)DQK);

    const int lmr = lane & 15;
    const int lmk = (lane >> 4) << 3;
    const uint32_t qsb = smem_u32(Qs), ksb = smem_u32(Ks);
    const uint32_t vsb = smem_u32(Vs), psb = smem_u32(Ps);
    const uint32_t qa_off = qsb + ((uint32_t)(r0 + lmr) * QST + lmk) * 2;
    const uint32_t kb_off = ksb + ((uint32_t)lmr * QST + lmk) * 2;
    const uint32_t pa_off = psb + ((uint32_t)(r0 + lmr) * PST + lmk) * 2;
    const uint32_t vb_off = vsb + ((uint32_t)lmr * VST + lmk) * 2;

    for (int f = tid; f < 128 * 24; f += 256) {
        int r = f / 24, c = (f % 24) << 3;
        *reinterpret_cast<float4*>(&Qs[r * QST + c]) =
            *reinterpret_cast<const float4*>(
                &q[(tokbase + q0 + r) * (NH * DQK) + h * DQK + c]);
    }

    float m_[2] = {-1e30f, -1e30f};
    float l_[2] = {0.f, 0.f};
    float o[16][4];
    #pragma unroll
    for (int nt = 0; nt < 16; nt++)
        #pragma unroll
        for (int r = 0; r < 4; r++) o[nt][r] = 0.f;

    for (int kb = 0; kb < S_LEN; kb += 64) {
        __syncthreads();
        for (int f = tid; f < 64 * 24; f += 256) {
            int r = f / 24, c = (f % 24) << 3;
            float4 v;
            if (c < DN)
                v = *reinterpret_cast<const float4*>(
                    &kv[(tokbase + kb + r) * (NH * 256) + h * 256 + c]);
            else
                v = *reinterpret_cast<const float4*>(
                    &kr[(tokbase + kb + r) * DR + (c - DN)]);
            *reinterpret_cast<float4*>(&Ks[r * QST + c]) = v;
        }
        for (int f = tid; f < 64 * 16; f += 256) {
            int r = f & 63, dg = (f >> 6) << 3;
            float4 v = *reinterpret_cast<const float4*>(
                &kv[(tokbase + kb + r) * (NH * 256) + h * 256 + DN + dg]);
            const __half* hv = reinterpret_cast<const __half*>(&v);
            #pragma unroll
            for (int i = 0; i < 8; i++) Vs[(dg + i) * VST + r] = hv[i];
        }
        __syncthreads();

        // ---- S = Q @ K^T : warp 16x64 ----
        float s[8][4];
        #pragma unroll
        for (int nt = 0; nt < 8; nt++)
            #pragma unroll
            for (int r = 0; r < 4; r++) s[nt][r] = 0.f;

        #pragma unroll
        for (int ks = 0; ks < 12; ks++) {
            const uint32_t kby = (uint32_t)(ks << 4) * 2;
            uint32_t af[4];
            ldmx4(af, qa_off + kby);
            #pragma unroll
            for (int ntp = 0; ntp < 4; ntp++) {
                uint32_t bf[4];
                ldmx4(bf, kb_off + (uint32_t)(ntp << 4) * QST * 2 + kby);
                mma_f16(s[2 * ntp],     af[0], af[1], af[2], af[3], bf[0], bf[2]);
                mma_f16(s[2 * ntp + 1], af[0], af[1], af[2], af[3], bf[1], bf[3]);
            }
        }

        // ---- online softmax ----
        #pragma unroll
        for (int hr = 0; hr < 2; hr++) {
            float mx = -1e30f;
            #pragma unroll
            for (int nt = 0; nt < 8; nt++) {
                s[nt][2 * hr]     *= scale;
                s[nt][2 * hr + 1] *= scale;
                mx = fmaxf(mx, fmaxf(s[nt][2 * hr], s[nt][2 * hr + 1]));
            }
            mx = fmaxf(mx, __shfl_xor_sync(~0u, mx, 1));
            mx = fmaxf(mx, __shfl_xor_sync(~0u, mx, 2));
            float nm = fmaxf(m_[hr], mx);
            float alpha = __expf(m_[hr] - nm);
            float ls = 0.f;
            #pragma unroll
            for (int nt = 0; nt < 8; nt++) {
                float p0 = __expf(s[nt][2 * hr] - nm);
                float p1 = __expf(s[nt][2 * hr + 1] - nm);
                s[nt][2 * hr] = p0; s[nt][2 * hr + 1] = p1;
                ls += p0 + p1;
            }
            ls += __shfl_xor_sync(~0u, ls, 1);
            ls += __shfl_xor_sync(~0u, ls, 2);
            l_[hr] = l_[hr] * alpha + ls;
            m_[hr] = nm;
            #pragma unroll
            for (int nt = 0; nt < 16; nt++) {
                o[nt][2 * hr]     *= alpha;
                o[nt][2 * hr + 1] *= alpha;
            }
            int pr = r0 + gp + (hr << 3);
            #pragma unroll
            for (int nt = 0; nt < 8; nt++)
                sth2(&Ps[pr * PST + (nt << 3) + (tg << 1)],
                     pkh2(s[nt][2 * hr], s[nt][2 * hr + 1]));
        }
        __syncwarp();

        // ---- O += P @ V : warp 16x128 ----
        #pragma unroll
        for (int ks = 0; ks < 4; ks++) {
            const uint32_t kby = (uint32_t)(ks << 4) * 2;
            uint32_t af[4];
            ldmx4(af, pa_off + kby);
            #pragma unroll
            for (int ntp = 0; ntp < 8; ntp++) {
                uint32_t bf[4];
                ldmx4(bf, vb_off + (uint32_t)(ntp << 4) * VST * 2 + kby);
                mma_f16(o[2 * ntp],     af[0], af[1], af[2], af[3], bf[0], bf[2]);
                mma_f16(o[2 * ntp + 1], af[0], af[1], af[2], af[3], bf[1], bf[3]);
            }
        }
    }

    float inv0 = 1.0f / l_[0], inv1 = 1.0f / l_[1];
    size_t rlo = (tokbase + q0 + r0 + gp) * (size_t)(NH * DVV) + h * DVV;
    size_t rhi = (tokbase + q0 + r0 + gp + 8) * (size_t)(NH * DVV) + h * DVV;
    #pragma unroll
    for (int nt = 0; nt < 16; nt++) {
        int col = (nt << 3) + (tg << 1);
        sth2(&ao[rlo + col], pkh2(o[nt][0] * inv0, o[nt][1] * inv0));
        sth2(&ao[rhi + col], pkh2(o[nt][2] * inv1, o[nt][3] * inv1));
    }
}

// ---------------- launch --------------------------------------------------------
extern "C" void kernel_launch(void* const* d_in, const int* in_sizes, int n_in,
                              void* d_out, int out_size)
{
    const float* hidden  = (const float*)d_in[0];
    const float* cosb    = (const float*)d_in[1];
    const float* sinb    = (const float*)d_in[2];
    const float* q_a_w   = (const float*)d_in[3];
    const float* q_a_ln  = (const float*)d_in[4];
    const float* q_b_w   = (const float*)d_in[5];
    const float* kv_a_w  = (const float*)d_in[6];
    const float* kv_a_ln = (const float*)d_in[7];
    const float* kv_b_w  = (const float*)d_in[8];
    const float* o_w     = (const float*)d_in[9];
    float* out = (float*)d_out;

    __half *qa, *qq, *ckv, *ckn, *kvf, *kr, *ao, *hid;
    __half *wqaT, *wqbT, *wkvaT, *wkvbT, *woT;
    cudaGetSymbolAddress((void**)&qa,    g_qa);
    cudaGetSymbolAddress((void**)&qq,    g_q);
    cudaGetSymbolAddress((void**)&ckv,   g_ckv);
    cudaGetSymbolAddress((void**)&ckn,   g_ckn);
    cudaGetSymbolAddress((void**)&kvf,   g_kv);
    cudaGetSymbolAddress((void**)&kr,    g_kr);
    cudaGetSymbolAddress((void**)&ao,    g_ao);
    cudaGetSymbolAddress((void**)&hid,   g_hid);
    cudaGetSymbolAddress((void**)&wqaT,  g_wqaT);
    cudaGetSymbolAddress((void**)&wqbT,  g_wqbT);
    cudaGetSymbolAddress((void**)&wkvaT, g_wkvaT);
    cudaGetSymbolAddress((void**)&wkvbT, g_wkvbT);
    cudaGetSymbolAddress((void**)&woT,   g_woT);

    cudaFuncSetAttribute(attn_f16,
        cudaFuncAttributeMaxDynamicSharedMemorySize, ATTN_SMEM_BYTES);
    cudaFuncSetAttribute(gemm_f16k,
        cudaFuncAttributeMaxDynamicSharedMemorySize, GEMM_SMEM);

    // [0] hidden -> fp16
    round_h<<<(NTOK * HID / 4 + 255) / 256, 256>>>(hidden, hid, NTOK * HID / 4);

    // [1] transpose weights -> fp16 [N][K]
    TAll ta;
    ta.p[0] = {q_a_w,  wqaT,  HID, QL,       QL};
    ta.p[1] = {q_b_w,  wqbT,  QL,  NH * DQK, NH * DQK};
    ta.p[2] = {kv_a_w, wkvaT, HID, CKV_W,    768};
    ta.p[3] = {kv_b_w, wkvbT, KVL, NH * 256, NH * 256};
    ta.p[4] = {o_w,    woT,   HID, HID,      HID};
    transpose_h<<<dim3(128, 64, 5), dim3(32, 8)>>>(ta);

    // [2] q_a = hid @ q_a_w
    gemm_f16k<<<dim3(QL / 128, NTOK / 128), 256, GEMM_SMEM>>>(hid, wqaT, qa, NTOK, QL, HID, 0);
    // [3] ckv = hid @ kv_a_w
    gemm_f16k<<<dim3(5, NTOK / 128), 256, GEMM_SMEM>>>(hid, wkvaT, ckv, NTOK, CKV_W, HID, 0);
    // [4] rmsnorm q_a (in place)
    rmsnorm_h<<<NTOK, 256>>>(qa, q_a_ln, qa, QL, QL, QL);
    // [5] q = qa @ q_b_w
    gemm_f16k<<<dim3(NH * DQK / 128, NTOK / 128), 256, GEMM_SMEM>>>(qa, wqbT, qq, NTOK, NH * DQK, QL, 0);
    // [6] rmsnorm ckv -> ckn
    rmsnorm_h<<<NTOK, 256>>>(ckv, kv_a_ln, ckn, CKV_W, KVL, KVL);
    // [7] kv = ckn @ kv_b_w
    gemm_f16k<<<dim3(NH * 256 / 128, NTOK / 128), 256, GEMM_SMEM>>>(ckn, wkvbT, kvf, NTOK, NH * 256, KVL, 0);
    // [8] rope q (in place)
    rope_q_h<<<NTOK, NH * 32>>>(qq, cosb, sinb);
    // [9] rope k_rope -> kr
    rope_k_h<<<NTOK, 32>>>(ckv, cosb, sinb, kr);
    // [10] attention
    attn_f16<<<dim3(S_LEN / 128, BATCH * NH), 256, ATTN_SMEM_BYTES>>>(qq, kvf, kr, ao);
    // [11] out = ao @ o_w (fp32 out)
    gemm_f16k<<<dim3(HID / 128, NTOK / 128), 256, GEMM_SMEM>>>(ao, woT, out, NTOK, HID, HID, 1);
}

// round 16
// speedup vs baseline: 9.1024x; 1.0961x over previous
#include <cuda_runtime.h>
#include <cuda_fp16.h>
#include <math.h>
#include <stdint.h>

#define S_LEN   2048
#define BATCH   2
#define NH      16
#define HID     2048
#define QL      1536
#define KVL     512
#define DR      64
#define DN      128
#define DVV     128
#define DQK     192
#define NTOK    (BATCH * S_LEN)     // 4096
#define CKV_W   (KVL + DR)          // 576

// ---------------- scratch (static device globals, fp16) ----------------------
__device__ __half g_qa [NTOK * QL];
__device__ __half g_q  [NTOK * NH * DQK];
__device__ __half g_ckv[NTOK * CKV_W];
__device__ __half g_ckn[NTOK * KVL];
__device__ __half g_kv [NTOK * NH * 256];
__device__ __half g_kr [NTOK * DR];
__device__ __half g_ao [NTOK * NH * DVV];
__device__ __half g_hid [NTOK * HID];
__device__ __half g_wqaT [QL * HID];
__device__ __half g_wqbT [NH * DQK * QL];
__device__ __half g_wkvaT[768 * HID];          // 576 padded to 768 rows
__device__ __half g_wkvbT[NH * 256 * KVL];
__device__ __half g_woT  [HID * HID];

// ---------------- helpers -----------------------------------------------------
__device__ __forceinline__ void sth2(__half* p, uint32_t v) {
    *reinterpret_cast<uint32_t*>(p) = v;
}
__device__ __forceinline__ uint32_t pkh2(float a, float b) {
    __half2 h = __floats2half2_rn(a, b);
    return *reinterpret_cast<uint32_t*>(&h);
}
__device__ __forceinline__ void mma_f16(float (&c)[4],
    uint32_t a0, uint32_t a1, uint32_t a2, uint32_t a3,
    uint32_t b0, uint32_t b1)
{
    asm volatile(
        "mma.sync.aligned.m16n8k16.row.col.f32.f16.f16.f32 "
        "{%0,%1,%2,%3},{%4,%5,%6,%7},{%8,%9},{%0,%1,%2,%3};"
        : "+f"(c[0]), "+f"(c[1]), "+f"(c[2]), "+f"(c[3])
        : "r"(a0), "r"(a1), "r"(a2), "r"(a3), "r"(b0), "r"(b1));
}
__device__ __forceinline__ void ldmx4(uint32_t (&r)[4], uint32_t addr) {
    asm volatile("ldmatrix.sync.aligned.m8n8.x4.shared.b16 {%0,%1,%2,%3}, [%4];"
        : "=r"(r[0]), "=r"(r[1]), "=r"(r[2]), "=r"(r[3]) : "r"(addr));
}
__device__ __forceinline__ void ldmx4t(uint32_t (&r)[4], uint32_t addr) {
    asm volatile("ldmatrix.sync.aligned.m8n8.x4.trans.shared.b16 {%0,%1,%2,%3}, [%4];"
        : "=r"(r[0]), "=r"(r[1]), "=r"(r[2]), "=r"(r[3]) : "r"(addr));
}
__device__ __forceinline__ uint32_t smem_u32(const void* p) {
    uint32_t a;
    asm("{ .reg .u64 t; cvta.to.shared.u64 t, %1; cvt.u32.u64 %0, t; }"
        : "=r"(a) : "l"(p));
    return a;
}
__device__ __forceinline__ void cp16u(uint32_t dst, const void* src) {
    asm volatile("cp.async.cg.shared.global [%0], [%1], 16;\n"
                 :: "r"(dst), "l"(src));
}
__device__ __forceinline__ void cp_commit() { asm volatile("cp.async.commit_group;\n"); }
__device__ __forceinline__ void cp_wait0()  { asm volatile("cp.async.wait_group 0;\n" ::: "memory"); }
__device__ __forceinline__ void cp_wait1()  { asm volatile("cp.async.wait_group 1;\n" ::: "memory"); }

// ---------------- fp16 GEMM (unchanged from R10 passing version) ---------------
#define GST 72
#define GEMM_SMEM (4 * 128 * GST * 2)

__global__ __launch_bounds__(256, 2) void gemm_f16k(
    const __half* __restrict__ A, const __half* __restrict__ Bt,
    void* __restrict__ Cv, int M, int N, int K, int fp32_out)
{
    extern __shared__ __half gsm[];
    const int tid = threadIdx.x;
    const int wid = tid >> 5, lane = tid & 31;
    const int wm = wid >> 2, wn = wid & 3;
    const int row0 = blockIdx.y << 7;
    const int col0 = blockIdx.x << 7;
    const int NS = K >> 6;

    const uint32_t smb = smem_u32(gsm);
    const uint32_t stA[2] = {smb,                     smb + 2u * 128 * GST * 2};
    const uint32_t stB[2] = {smb + 128u * GST * 2,    smb + 3u * 128 * GST * 2};

    const int lmr = lane & 15;
    const int lmk = (lane >> 4) << 3;
    const uint32_t a_off = ((uint32_t)((wm << 6) + lmr) * GST + lmk) * 2;
    const uint32_t b_off = ((uint32_t)((wn << 5) + lmr) * GST + lmk) * 2;

    float acc[4][4][4];
    #pragma unroll
    for (int mt = 0; mt < 4; mt++)
        #pragma unroll
        for (int nt = 0; nt < 4; nt++)
            #pragma unroll
            for (int r = 0; r < 4; r++) acc[mt][nt][r] = 0.f;

    #pragma unroll
    for (int i = 0; i < 4; i++) {
        int c = tid + (i << 8);
        int r = c >> 3, kc = (c & 7) << 3;
        cp16u(stA[0] + ((uint32_t)r * GST + kc) * 2, A  + (size_t)(row0 + r) * K + kc);
        cp16u(stB[0] + ((uint32_t)r * GST + kc) * 2, Bt + (size_t)(col0 + r) * K + kc);
    }
    cp_commit();

    for (int s = 0; s < NS; s++) {
        const int b = s & 1;
        if (s + 1 < NS) {
            const int nb = b ^ 1;
            const int k0 = (s + 1) << 6;
            #pragma unroll
            for (int i = 0; i < 4; i++) {
                int c = tid + (i << 8);
                int r = c >> 3, kc = (c & 7) << 3;
                cp16u(stA[nb] + ((uint32_t)r * GST + kc) * 2, A  + (size_t)(row0 + r) * K + k0 + kc);
                cp16u(stB[nb] + ((uint32_t)r * GST + kc) * 2, Bt + (size_t)(col0 + r) * K + k0 + kc);
            }
            cp_commit();
            cp_wait1();
        } else {
            cp_wait0();
        }
        __syncthreads();

        const uint32_t ab = stA[b] + a_off;
        const uint32_t bb = stB[b] + b_off;
        #pragma unroll
        for (int ks = 0; ks < 4; ks++) {
            const uint32_t kby = (uint32_t)(ks << 4) * 2;
            uint32_t af[4][4];
            #pragma unroll
            for (int mt = 0; mt < 4; mt++)
                ldmx4(af[mt], ab + (uint32_t)(mt << 4) * GST * 2 + kby);
            #pragma unroll
            for (int ntp = 0; ntp < 2; ntp++) {
                uint32_t bf[4];
                ldmx4(bf, bb + (uint32_t)(ntp << 4) * GST * 2 + kby);
                #pragma unroll
                for (int mt = 0; mt < 4; mt++) {
                    mma_f16(acc[mt][2 * ntp],     af[mt][0], af[mt][1], af[mt][2], af[mt][3], bf[0], bf[2]);
                    mma_f16(acc[mt][2 * ntp + 1], af[mt][0], af[mt][1], af[mt][2], af[mt][3], bf[1], bf[3]);
                }
            }
        }
        __syncthreads();
    }

    const int tg = lane & 3, gp = lane >> 2;
    #pragma unroll
    for (int mt = 0; mt < 4; mt++) {
        int row = row0 + (wm << 6) + (mt << 4) + gp;
        #pragma unroll
        for (int nt = 0; nt < 4; nt++) {
            int col = col0 + (wn << 5) + (nt << 3) + (tg << 1);
            if (col < N) {
                if (fp32_out) {
                    float* C = (float*)Cv;
                    *reinterpret_cast<float2*>(&C[(size_t)row * N + col]) =
                        make_float2(acc[mt][nt][0], acc[mt][nt][1]);
                    *reinterpret_cast<float2*>(&C[(size_t)(row + 8) * N + col]) =
                        make_float2(acc[mt][nt][2], acc[mt][nt][3]);
                } else {
                    __half* C = (__half*)Cv;
                    sth2(&C[(size_t)row * N + col], pkh2(acc[mt][nt][0], acc[mt][nt][1]));
                    sth2(&C[(size_t)(row + 8) * N + col], pkh2(acc[mt][nt][2], acc[mt][nt][3]));
                }
            }
        }
    }
}

// ---------------- hidden -> fp16 ----------------------------------------------
__global__ void round_h(const float* __restrict__ in, __half* __restrict__ out, int n4)
{
    int i = blockIdx.x * blockDim.x + threadIdx.x;
    if (i < n4) {
        float4 v = reinterpret_cast<const float4*>(in)[i];
        reinterpret_cast<uint2*>(out)[i] = make_uint2(pkh2(v.x, v.y), pkh2(v.z, v.w));
    }
}

// ---------------- weight transpose -> fp16 [N][K] ------------------------------
struct TParams { const float* src; __half* dst; int R, C, Cpad; };
struct TAll { TParams p[5]; };

__global__ void transpose_h(TAll t)
{
    const TParams pp = t.p[blockIdx.z];
    const int cx = blockIdx.x << 5, ry = blockIdx.y << 5;
    if (cx >= pp.Cpad || ry >= pp.R) return;
    __shared__ float tile[32][33];
    #pragma unroll
    for (int i = 0; i < 4; i++) {
        int r = ry + threadIdx.y + (i << 3);
        int c = cx + threadIdx.x;
        float v = 0.f;
        if (r < pp.R && c < pp.C) v = pp.src[(size_t)r * pp.C + c];
        tile[threadIdx.y + (i << 3)][threadIdx.x] = v;
    }
    __syncthreads();
    #pragma unroll
    for (int i = 0; i < 4; i++) {
        int outr = cx + threadIdx.y + (i << 3);
        int outc = ry + threadIdx.x;
        if (outr < pp.Cpad && outc < pp.R)
            pp.dst[(size_t)outr * pp.R + outc] = __float2half_rn(tile[threadIdx.x][threadIdx.y + (i << 3)]);
    }
}

// ---------------- RMSNorm (fp16 in/out, fp32 math) -----------------------------
__global__ __launch_bounds__(256) void rmsnorm_h(
    const __half* __restrict__ in, const float* __restrict__ w,
    __half* __restrict__ out, int in_stride, int out_stride, int n)
{
    const int row = blockIdx.x;
    const __half* x = in + (size_t)row * in_stride;
    float ss = 0.f;
    for (int j = threadIdx.x; j < n; j += 256) { float v = __half2float(x[j]); ss += v * v; }
    __shared__ float red[8];
    #pragma unroll
    for (int off = 16; off; off >>= 1) ss += __shfl_xor_sync(~0u, ss, off);
    if ((threadIdx.x & 31) == 0) red[threadIdx.x >> 5] = ss;
    __syncthreads();
    if (threadIdx.x == 0) {
        float t = 0.f;
        #pragma unroll
        for (int i = 0; i < 8; i++) t += red[i];
        red[0] = rsqrtf(t / n + 1e-6f);
    }
    __syncthreads();
    const float r = red[0];
    __half* y = out + (size_t)row * out_stride;
    for (int j = threadIdx.x; j < n; j += 256)
        y[j] = __float2half_rn(w[j] * __half2float(x[j]) * r);
}

// ---------------- RoPE (fp16) ---------------------------------------------------
__global__ void rope_q_h(__half* __restrict__ q,
                         const float* __restrict__ cosb,
                         const float* __restrict__ sinb)
{
    const int t = blockIdx.x;
    const int h = threadIdx.x >> 5;
    const int i = threadIdx.x & 31;
    const int s = t & (S_LEN - 1);
    const float cv = cosb[s * DR + 2 * i];
    const float sv = sinb[s * DR + 2 * i];
    __half* p = q + (size_t)t * NH * DQK + h * DQK + DN + 2 * i;
    const float xr = __half2float(p[0]), xi = __half2float(p[1]);
    sth2(p, pkh2(xr * cv - xi * sv, xr * sv + xi * cv));
}

__global__ void rope_k_h(const __half* __restrict__ ckv,
                         const float* __restrict__ cosb,
                         const float* __restrict__ sinb,
                         __half* __restrict__ kr)
{
    const int t = blockIdx.x;
    const int i = threadIdx.x;
    const int s = t & (S_LEN - 1);
    const float cv = cosb[s * DR + 2 * i];
    const float sv = sinb[s * DR + 2 * i];
    const float xr = __half2float(ckv[(size_t)t * CKV_W + KVL + 2 * i]);
    const float xi = __half2float(ckv[(size_t)t * CKV_W + KVL + 2 * i + 1]);
    sth2(&kr[t * DR + 2 * i], pkh2(xr * cv - xi * sv, xr * sv + xi * cv));
}

// ---------------- Flash attention: cp.async double-buffered K/V -----------------
#define QST 200
#define VST 136
#define PST 72
#define SH_Q  0
#define SH_K0 (SH_Q + 128 * QST)
#define SH_K1 (SH_K0 + 64 * QST)
#define SH_V0 (SH_K1 + 64 * QST)
#define SH_V1 (SH_V0 + 64 * VST)
#define SH_P  (SH_V1 + 64 * VST)
#define ATTN_SMEM_BYTES ((SH_P + 128 * PST) * 2)

__device__ __forceinline__ void attn_stage_kv(
    uint32_t kdst, uint32_t vdst,
    const __half* kvp, const __half* krp, int tid)
{
    #pragma unroll
    for (int i = 0; i < 6; i++) {
        int idx = tid + (i << 8);
        int r = idx / 24, c = idx - r * 24;
        const __half* src = (c < 16)
            ? kvp + (size_t)r * (NH * 256) + (c << 3)
            : krp + (size_t)r * DR + ((c - 16) << 3);
        cp16u(kdst + ((uint32_t)r * QST + (c << 3)) * 2, src);
    }
    #pragma unroll
    for (int i = 0; i < 4; i++) {
        int idx = tid + (i << 8);
        int r = idx >> 4, c = idx & 15;
        cp16u(vdst + ((uint32_t)r * VST + (c << 3)) * 2,
              kvp + (size_t)r * (NH * 256) + DN + (c << 3));
    }
}

__global__ __launch_bounds__(256) void attn_f16(
    const __half* __restrict__ q, const __half* __restrict__ kv,
    const __half* __restrict__ kr, __half* __restrict__ ao)
{
    extern __shared__ __half sh[];
    __half* Qs = sh + SH_Q;
    __half* Ps = sh + SH_P;

    const int tid = threadIdx.x;
    const int wid = tid >> 5, lane = tid & 31;
    const int tg = lane & 3, gp = lane >> 2;
    const int r0 = wid << 4;
    const int bh = blockIdx.y;
    const int b = bh >> 4, h = bh & 15;
    const int q0 = blockIdx.x << 7;
    const size_t tokbase = (size_t)b * S_LEN;
    const float scale = rsqrtf((float)DQK);

    const int lmr = lane & 15;
    const int lmk = (lane >> 4) << 3;
    const uint32_t shb = smem_u32(sh);
    const uint32_t kbuf[2] = {shb + SH_K0 * 2u, shb + SH_K1 * 2u};
    const uint32_t vbuf[2] = {shb + SH_V0 * 2u, shb + SH_V1 * 2u};
    const uint32_t qa_off = shb + ((uint32_t)(r0 + lmr) * QST + lmk) * 2;
    const uint32_t pa_off = shb + SH_P * 2u + ((uint32_t)(r0 + lmr) * PST + lmk) * 2;
    const uint32_t klane = ((uint32_t)lmr * QST + lmk) * 2;
    const uint32_t vlane = ((uint32_t)lmr * VST + lmk) * 2;

    const __half* kvbase = kv + (tokbase) * (NH * 256) + h * 256;
    const __half* krbase = kr + (tokbase) * DR;

    for (int f = tid; f < 128 * 24; f += 256) {
        int r = f / 24, c = (f % 24) << 3;
        *reinterpret_cast<float4*>(&Qs[r * QST + c]) =
            *reinterpret_cast<const float4*>(
                &q[(tokbase + q0 + r) * (NH * DQK) + h * DQK + c]);
    }
    attn_stage_kv(kbuf[0], vbuf[0], kvbase, krbase, tid);
    cp_commit();

    float m_[2] = {-1e30f, -1e30f};
    float l_[2] = {0.f, 0.f};
    float o[16][4];
    #pragma unroll
    for (int nt = 0; nt < 16; nt++)
        #pragma unroll
        for (int r = 0; r < 4; r++) o[nt][r] = 0.f;

    const int NB = S_LEN / 64;
    for (int kbi = 0; kbi < NB; kbi++) {
        const int bsel = kbi & 1;
        __syncthreads();
        if (kbi + 1 < NB) {
            attn_stage_kv(kbuf[bsel ^ 1], vbuf[bsel ^ 1],
                          kvbase + (size_t)(kbi + 1) * 64 * (NH * 256),
                          krbase + (size_t)(kbi + 1) * 64 * DR, tid);
            cp_commit();
            cp_wait1();
        } else {
            cp_wait0();
        }
        __syncthreads();

        const uint32_t ka = kbuf[bsel] + klane;
        const uint32_t va = vbuf[bsel] + vlane;

        float s[8][4];
        #pragma unroll
        for (int nt = 0; nt < 8; nt++)
            #pragma unroll
            for (int r = 0; r < 4; r++) s[nt][r] = 0.f;

        #pragma unroll
        for (int ks = 0; ks < 12; ks++) {
            const uint32_t kby = (uint32_t)(ks << 5);
            uint32_t af[4];
            ldmx4(af, qa_off + kby);
            #pragma unroll
            for (int ntp = 0; ntp < 4; ntp++) {
                uint32_t bf[4];
                ldmx4(bf, ka + (uint32_t)(ntp << 4) * QST * 2 + kby);
                mma_f16(s[2 * ntp],     af[0], af[1], af[2], af[3], bf[0], bf[2]);
                mma_f16(s[2 * ntp + 1], af[0], af[1], af[2], af[3], bf[1], bf[3]);
            }
        }

        #pragma unroll
        for (int hr = 0; hr < 2; hr++) {
            float mx = -1e30f;
            #pragma unroll
            for (int nt = 0; nt < 8; nt++) {
                s[nt][2 * hr]     *= scale;
                s[nt][2 * hr + 1] *= scale;
                mx = fmaxf(mx, fmaxf(s[nt][2 * hr], s[nt][2 * hr + 1]));
            }
            mx = fmaxf(mx, __shfl_xor_sync(~0u, mx, 1));
            mx = fmaxf(mx, __shfl_xor_sync(~0u, mx, 2));
            float nm = fmaxf(m_[hr], mx);
            float alpha = __expf(m_[hr] - nm);
            float ls = 0.f;
            #pragma unroll
            for (int nt = 0; nt < 8; nt++) {
                float p0 = __expf(s[nt][2 * hr] - nm);
                float p1 = __expf(s[nt][2 * hr + 1] - nm);
                s[nt][2 * hr] = p0; s[nt][2 * hr + 1] = p1;
                ls += p0 + p1;
            }
            ls += __shfl_xor_sync(~0u, ls, 1);
            ls += __shfl_xor_sync(~0u, ls, 2);
            l_[hr] = l_[hr] * alpha + ls;
            m_[hr] = nm;
            #pragma unroll
            for (int nt = 0; nt < 16; nt++) {
                o[nt][2 * hr]     *= alpha;
                o[nt][2 * hr + 1] *= alpha;
            }
            int pr = r0 + gp + (hr << 3);
            #pragma unroll
            for (int nt = 0; nt < 8; nt++)
                sth2(&Ps[pr * PST + (nt << 3) + (tg << 1)],
                     pkh2(s[nt][2 * hr], s[nt][2 * hr + 1]));
        }
        __syncwarp();

        #pragma unroll
        for (int ks = 0; ks < 4; ks++) {
            const uint32_t kof = (uint32_t)(ks << 4) * VST * 2;
            uint32_t af[4];
            ldmx4(af, pa_off + (uint32_t)(ks << 5));
            #pragma unroll
            for (int ntp = 0; ntp < 8; ntp++) {
                uint32_t bf[4];
                ldmx4t(bf, va + kof + (uint32_t)(ntp << 4) * 2);
                mma_f16(o[2 * ntp],     af[0], af[1], af[2], af[3], bf[0], bf[1]);
                mma_f16(o[2 * ntp + 1], af[0], af[1], af[2], af[3], bf[2], bf[3]);
            }
        }
    }

    float inv0 = 1.0f / l_[0], inv1 = 1.0f / l_[1];
    size_t rlo = (tokbase + q0 + r0 + gp) * (size_t)(NH * DVV) + h * DVV;
    size_t rhi = (tokbase + q0 + r0 + gp + 8) * (size_t)(NH * DVV) + h * DVV;
    #pragma unroll
    for (int nt = 0; nt < 16; nt++) {
        int col = (nt << 3) + (tg << 1);
        sth2(&ao[rlo + col], pkh2(o[nt][0] * inv0, o[nt][1] * inv0));
        sth2(&ao[rhi + col], pkh2(o[nt][2] * inv1, o[nt][3] * inv1));
    }
}

// ---------------- launch --------------------------------------------------------
extern "C" void kernel_launch(void* const* d_in, const int* in_sizes, int n_in,
                              void* d_out, int out_size)
{
    const float* hidden  = (const float*)d_in[0];
    const float* cosb    = (const float*)d_in[1];
    const float* sinb    = (const float*)d_in[2];
    const float* q_a_w   = (const float*)d_in[3];
    const float* q_a_ln  = (const float*)d_in[4];
    const float* q_b_w   = (const float*)d_in[5];
    const float* kv_a_w  = (const float*)d_in[6];
    const float* kv_a_ln = (const float*)d_in[7];
    const float* kv_b_w  = (const float*)d_in[8];
    const float* o_w     = (const float*)d_in[9];
    float* out = (float*)d_out;

    __half *qa, *qq, *ckv, *ckn, *kvf, *kr, *ao, *hid;
    __half *wqaT, *wqbT, *wkvaT, *wkvbT, *woT;
    cudaGetSymbolAddress((void**)&qa,    g_qa);
    cudaGetSymbolAddress((void**)&qq,    g_q);
    cudaGetSymbolAddress((void**)&ckv,   g_ckv);
    cudaGetSymbolAddress((void**)&ckn,   g_ckn);
    cudaGetSymbolAddress((void**)&kvf,   g_kv);
    cudaGetSymbolAddress((void**)&kr,    g_kr);
    cudaGetSymbolAddress((void**)&ao,    g_ao);
    cudaGetSymbolAddress((void**)&hid,   g_hid);
    cudaGetSymbolAddress((void**)&wqaT,  g_wqaT);
    cudaGetSymbolAddress((void**)&wqbT,  g_wqbT);
    cudaGetSymbolAddress((void**)&wkvaT, g_wkvaT);
    cudaGetSymbolAddress((void**)&wkvbT, g_wkvbT);
    cudaGetSymbolAddress((void**)&woT,   g_woT);

    cudaFuncSetAttribute(attn_f16,
        cudaFuncAttributeMaxDynamicSharedMemorySize, ATTN_SMEM_BYTES);
    cudaFuncSetAttribute(gemm_f16k,
        cudaFuncAttributeMaxDynamicSharedMemorySize, GEMM_SMEM);

    // [0] hidden -> fp16
    round_h<<<(NTOK * HID / 4 + 255) / 256, 256>>>(hidden, hid, NTOK * HID / 4);

    // [1] transpose weights -> fp16 [N][K]
    TAll ta;
    ta.p[0] = {q_a_w,  wqaT,  HID, QL,       QL};
    ta.p[1] = {q_b_w,  wqbT,  QL,  NH * DQK, NH * DQK};
    ta.p[2] = {kv_a_w, wkvaT, HID, CKV_W,    768};
    ta.p[3] = {kv_b_w, wkvbT, KVL, NH * 256, NH * 256};
    ta.p[4] = {o_w,    woT,   HID, HID,      HID};
    transpose_h<<<dim3(128, 64, 5), dim3(32, 8)>>>(ta);

    // [2] q_a = hid @ q_a_w
    gemm_f16k<<<dim3(QL / 128, NTOK / 128), 256, GEMM_SMEM>>>(hid, wqaT, qa, NTOK, QL, HID, 0);
    // [3] ckv = hid @ kv_a_w
    gemm_f16k<<<dim3(5, NTOK / 128), 256, GEMM_SMEM>>>(hid, wkvaT, ckv, NTOK, CKV_W, HID, 0);
    // [4] rmsnorm q_a (in place)
    rmsnorm_h<<<NTOK, 256>>>(qa, q_a_ln, qa, QL, QL, QL);
    // [5] q = qa @ q_b_w
    gemm_f16k<<<dim3(NH * DQK / 128, NTOK / 128), 256, GEMM_SMEM>>>(qa, wqbT, qq, NTOK, NH * DQK, QL, 0);
    // [6] rmsnorm ckv -> ckn
    rmsnorm_h<<<NTOK, 256>>>(ckv, kv_a_ln, ckn, CKV_W, KVL, KVL);
    // [7] kv = ckn @ kv_b_w
    gemm_f16k<<<dim3(NH * 256 / 128, NTOK / 128), 256, GEMM_SMEM>>>(ckn, wkvbT, kvf, NTOK, NH * 256, KVL, 0);
    // [8] rope q (in place)
    rope_q_h<<<NTOK, NH * 32>>>(qq, cosb, sinb);
    // [9] rope k_rope -> kr
    rope_k_h<<<NTOK, 32>>>(ckv, cosb, sinb, kr);
    // [10] attention
    attn_f16<<<dim3(S_LEN / 128, BATCH * NH), 256, ATTN_SMEM_BYTES>>>(qq, kvf, kr, ao);
    // [11] out = ao @ o_w (fp32 out)
    gemm_f16k<<<dim3(HID / 128, NTOK / 128), 256, GEMM_SMEM>>>(ao, woT, out, NTOK, HID, HID, 1);
}

// round 17
// speedup vs baseline: 9.1127x; 1.0011x over previous
#include <cuda_runtime.h>
#include <cuda_fp16.h>
#include <math.h>
#include <stdint.h>

#define S_LEN   2048
#define BATCH   2
#define NH      16
#define HID     2048
#define QL      1536
#define KVL     512
#define DR      64
#define DN      128
#define DVV     128
#define DQK     192
#define NTOK    (BATCH * S_LEN)     // 4096
#define CKV_W   (KVL + DR)          // 576
#define QAC_W   2176                // QL + 640 (ckv padded to 640)

// ---------------- scratch (static device globals, fp16) ----------------------
__device__ __half g_qac[NTOK * QAC_W];         // fused q_a | ckv output
__device__ __half g_qa [NTOK * QL];            // rmsnorm(q_a)
__device__ __half g_q  [NTOK * NH * DQK];
__device__ __half g_ckn[NTOK * KVL];
__device__ __half g_kv [NTOK * NH * 256];
__device__ __half g_kr [NTOK * DR];
__device__ __half g_ao [NTOK * NH * DVV];
__device__ __half g_hid [NTOK * HID];
__device__ __half g_wabT [QAC_W * HID];        // [q_a_w^T (1536) | kv_a_w^T (640 pad)]
__device__ __half g_wqbT [NH * DQK * QL];
__device__ __half g_wkvbT[NH * 256 * KVL];
__device__ __half g_woT  [HID * HID];

// ---------------- helpers -----------------------------------------------------
__device__ __forceinline__ void sth2(__half* p, uint32_t v) {
    *reinterpret_cast<uint32_t*>(p) = v;
}
__device__ __forceinline__ uint32_t pkh2(float a, float b) {
    __half2 h = __floats2half2_rn(a, b);
    return *reinterpret_cast<uint32_t*>(&h);
}
__device__ __forceinline__ void mma_f16(float (&c)[4],
    uint32_t a0, uint32_t a1, uint32_t a2, uint32_t a3,
    uint32_t b0, uint32_t b1)
{
    asm volatile(
        "mma.sync.aligned.m16n8k16.row.col.f32.f16.f16.f32 "
        "{%0,%1,%2,%3},{%4,%5,%6,%7},{%8,%9},{%0,%1,%2,%3};"
        : "+f"(c[0]), "+f"(c[1]), "+f"(c[2]), "+f"(c[3])
        : "r"(a0), "r"(a1), "r"(a2), "r"(a3), "r"(b0), "r"(b1));
}
__device__ __forceinline__ void ldmx4(uint32_t (&r)[4], uint32_t addr) {
    asm volatile("ldmatrix.sync.aligned.m8n8.x4.shared.b16 {%0,%1,%2,%3}, [%4];"
        : "=r"(r[0]), "=r"(r[1]), "=r"(r[2]), "=r"(r[3]) : "r"(addr));
}
__device__ __forceinline__ void ldmx4t(uint32_t (&r)[4], uint32_t addr) {
    asm volatile("ldmatrix.sync.aligned.m8n8.x4.trans.shared.b16 {%0,%1,%2,%3}, [%4];"
        : "=r"(r[0]), "=r"(r[1]), "=r"(r[2]), "=r"(r[3]) : "r"(addr));
}
__device__ __forceinline__ uint32_t smem_u32(const void* p) {
    uint32_t a;
    asm("{ .reg .u64 t; cvta.to.shared.u64 t, %1; cvt.u32.u64 %0, t; }"
        : "=r"(a) : "l"(p));
    return a;
}
__device__ __forceinline__ void cp16u(uint32_t dst, const void* src) {
    asm volatile("cp.async.cg.shared.global [%0], [%1], 16;\n"
                 :: "r"(dst), "l"(src));
}
__device__ __forceinline__ void cp_commit() { asm volatile("cp.async.commit_group;\n"); }
__device__ __forceinline__ void cp_wait0()  { asm volatile("cp.async.wait_group 0;\n" ::: "memory"); }
__device__ __forceinline__ void cp_wait1()  { asm volatile("cp.async.wait_group 1;\n" ::: "memory"); }
__device__ __forceinline__ void cp_wait2()  { asm volatile("cp.async.wait_group 2;\n" ::: "memory"); }

// ---------------- fp16 GEMM: C[M,N] = A[M,K] @ Bt[N,K]^T ----------------------
// 128x128 block, BK=64, 3-stage cp.async, ldmatrix, 256 threads, warps 2x4.
#define GST 72
#define GSTAGE_B (2 * 128 * GST * 2)            // A+B bytes per stage = 36864
#define GEMM_SMEM (3 * GSTAGE_B)                // 110592

__global__ __launch_bounds__(256, 2) void gemm_f16k(
    const __half* __restrict__ A, const __half* __restrict__ Bt,
    void* __restrict__ Cv, int M, int N, int K, int fp32_out)
{
    extern __shared__ __half gsm[];
    const int tid = threadIdx.x;
    const int wid = tid >> 5, lane = tid & 31;
    const int wm = wid >> 2, wn = wid & 3;
    const int row0 = blockIdx.y << 7;
    const int col0 = blockIdx.x << 7;
    const int NS = K >> 6;

    const uint32_t smb = smem_u32(gsm);
    const uint32_t stA[3] = {smb, smb + GSTAGE_B, smb + 2u * GSTAGE_B};
    // B half of each stage
    const uint32_t boff = 128u * GST * 2;

    const int lmr = lane & 15;
    const int lmk = (lane >> 4) << 3;
    const uint32_t a_off = ((uint32_t)((wm << 6) + lmr) * GST + lmk) * 2;
    const uint32_t b_off = boff + ((uint32_t)((wn << 5) + lmr) * GST + lmk) * 2;

    float acc[4][4][4];
    #pragma unroll
    for (int mt = 0; mt < 4; mt++)
        #pragma unroll
        for (int nt = 0; nt < 4; nt++)
            #pragma unroll
            for (int r = 0; r < 4; r++) acc[mt][nt][r] = 0.f;

    // prologue: stage slabs 0 and 1
    #pragma unroll
    for (int ps = 0; ps < 2; ps++) {
        if (ps < NS) {
            const int k0 = ps << 6;
            #pragma unroll
            for (int i = 0; i < 4; i++) {
                int c = tid + (i << 8);
                int r = c >> 3, kc = (c & 7) << 3;
                cp16u(stA[ps] + ((uint32_t)r * GST + kc) * 2,
                      A + (size_t)(row0 + r) * K + k0 + kc);
                cp16u(stA[ps] + boff + ((uint32_t)r * GST + kc) * 2,
                      Bt + (size_t)(col0 + r) * K + k0 + kc);
            }
        }
        cp_commit();
    }

    int buf = 0;
    for (int s = 0; s < NS; s++) {
        if (s + 2 < NS) {
            const int nb = (s + 2) % 3;
            const int k0 = (s + 2) << 6;
            #pragma unroll
            for (int i = 0; i < 4; i++) {
                int c = tid + (i << 8);
                int r = c >> 3, kc = (c & 7) << 3;
                cp16u(stA[nb] + ((uint32_t)r * GST + kc) * 2,
                      A + (size_t)(row0 + r) * K + k0 + kc);
                cp16u(stA[nb] + boff + ((uint32_t)r * GST + kc) * 2,
                      Bt + (size_t)(col0 + r) * K + k0 + kc);
            }
            cp_commit();
            cp_wait2();
        } else if (s + 1 < NS) {
            cp_wait1();
        } else {
            cp_wait0();
        }
        __syncthreads();

        const uint32_t ab = stA[buf] + a_off;
        const uint32_t bb = stA[buf] + b_off;
        #pragma unroll
        for (int ks = 0; ks < 4; ks++) {
            const uint32_t kby = (uint32_t)(ks << 4) * 2;
            uint32_t af[4][4];
            #pragma unroll
            for (int mt = 0; mt < 4; mt++)
                ldmx4(af[mt], ab + (uint32_t)(mt << 4) * GST * 2 + kby);
            #pragma unroll
            for (int ntp = 0; ntp < 2; ntp++) {
                uint32_t bf[4];
                ldmx4(bf, bb + (uint32_t)(ntp << 4) * GST * 2 + kby);
                #pragma unroll
                for (int mt = 0; mt < 4; mt++) {
                    mma_f16(acc[mt][2 * ntp],     af[mt][0], af[mt][1], af[mt][2], af[mt][3], bf[0], bf[2]);
                    mma_f16(acc[mt][2 * ntp + 1], af[mt][0], af[mt][1], af[mt][2], af[mt][3], bf[1], bf[3]);
                }
            }
        }
        __syncthreads();
        buf = (buf + 1) % 3;
    }

    const int tg = lane & 3, gp = lane >> 2;
    #pragma unroll
    for (int mt = 0; mt < 4; mt++) {
        int row = row0 + (wm << 6) + (mt << 4) + gp;
        #pragma unroll
        for (int nt = 0; nt < 4; nt++) {
            int col = col0 + (wn << 5) + (nt << 3) + (tg << 1);
            if (col < N) {
                if (fp32_out) {
                    float* C = (float*)Cv;
                    *reinterpret_cast<float2*>(&C[(size_t)row * N + col]) =
                        make_float2(acc[mt][nt][0], acc[mt][nt][1]);
                    *reinterpret_cast<float2*>(&C[(size_t)(row + 8) * N + col]) =
                        make_float2(acc[mt][nt][2], acc[mt][nt][3]);
                } else {
                    __half* C = (__half*)Cv;
                    sth2(&C[(size_t)row * N + col], pkh2(acc[mt][nt][0], acc[mt][nt][1]));
                    sth2(&C[(size_t)(row + 8) * N + col], pkh2(acc[mt][nt][2], acc[mt][nt][3]));
                }
            }
        }
    }
}

// ---------------- hidden -> fp16 ----------------------------------------------
__global__ void round_h(const float* __restrict__ in, __half* __restrict__ out, int n4)
{
    int i = blockIdx.x * blockDim.x + threadIdx.x;
    if (i < n4) {
        float4 v = reinterpret_cast<const float4*>(in)[i];
        reinterpret_cast<uint2*>(out)[i] = make_uint2(pkh2(v.x, v.y), pkh2(v.z, v.w));
    }
}

// ---------------- weight transpose -> fp16 [N][K] ------------------------------
struct TParams { const float* src; __half* dst; int R, C, Cpad; };
struct TAll { TParams p[5]; };

__global__ void transpose_h(TAll t)
{
    const TParams pp = t.p[blockIdx.z];
    const int cx = blockIdx.x << 5, ry = blockIdx.y << 5;
    if (cx >= pp.Cpad || ry >= pp.R) return;
    __shared__ float tile[32][33];
    #pragma unroll
    for (int i = 0; i < 4; i++) {
        int r = ry + threadIdx.y + (i << 3);
        int c = cx + threadIdx.x;
        float v = 0.f;
        if (r < pp.R && c < pp.C) v = pp.src[(size_t)r * pp.C + c];
        tile[threadIdx.y + (i << 3)][threadIdx.x] = v;
    }
    __syncthreads();
    #pragma unroll
    for (int i = 0; i < 4; i++) {
        int outr = cx + threadIdx.y + (i << 3);
        int outc = ry + threadIdx.x;
        if (outr < pp.Cpad && outc < pp.R)
            pp.dst[(size_t)outr * pp.R + outc] = __float2half_rn(tile[threadIdx.x][threadIdx.y + (i << 3)]);
    }
}

// ---------------- RMSNorm (fp16 in/out, fp32 math) -----------------------------
__global__ __launch_bounds__(256) void rmsnorm_h(
    const __half* __restrict__ in, const float* __restrict__ w,
    __half* __restrict__ out, int in_stride, int out_stride, int n)
{
    const int row = blockIdx.x;
    const __half* x = in + (size_t)row * in_stride;
    float ss = 0.f;
    for (int j = threadIdx.x; j < n; j += 256) { float v = __half2float(x[j]); ss += v * v; }
    __shared__ float red[8];
    #pragma unroll
    for (int off = 16; off; off >>= 1) ss += __shfl_xor_sync(~0u, ss, off);
    if ((threadIdx.x & 31) == 0) red[threadIdx.x >> 5] = ss;
    __syncthreads();
    if (threadIdx.x == 0) {
        float t = 0.f;
        #pragma unroll
        for (int i = 0; i < 8; i++) t += red[i];
        red[0] = rsqrtf(t / n + 1e-6f);
    }
    __syncthreads();
    const float r = red[0];
    __half* y = out + (size_t)row * out_stride;
    for (int j = threadIdx.x; j < n; j += 256)
        y[j] = __float2half_rn(w[j] * __half2float(x[j]) * r);
}

// ---------------- RoPE (fp16) ---------------------------------------------------
__global__ void rope_q_h(__half* __restrict__ q,
                         const float* __restrict__ cosb,
                         const float* __restrict__ sinb)
{
    const int t = blockIdx.x;
    const int h = threadIdx.x >> 5;
    const int i = threadIdx.x & 31;
    const int s = t & (S_LEN - 1);
    const float cv = cosb[s * DR + 2 * i];
    const float sv = sinb[s * DR + 2 * i];
    __half* p = q + (size_t)t * NH * DQK + h * DQK + DN + 2 * i;
    const float xr = __half2float(p[0]), xi = __half2float(p[1]);
    sth2(p, pkh2(xr * cv - xi * sv, xr * sv + xi * cv));
}

// reads rope slice from combined qac buffer (stride QAC_W, offset QL+KVL)
__global__ void rope_k_h(const __half* __restrict__ qac,
                         const float* __restrict__ cosb,
                         const float* __restrict__ sinb,
                         __half* __restrict__ kr)
{
    const int t = blockIdx.x;
    const int i = threadIdx.x;
    const int s = t & (S_LEN - 1);
    const float cv = cosb[s * DR + 2 * i];
    const float sv = sinb[s * DR + 2 * i];
    const float xr = __half2float(qac[(size_t)t * QAC_W + QL + KVL + 2 * i]);
    const float xi = __half2float(qac[(size_t)t * QAC_W + QL + KVL + 2 * i + 1]);
    sth2(&kr[t * DR + 2 * i], pkh2(xr * cv - xi * sv, xr * sv + xi * cv));
}

// ---------------- Flash attention (unchanged from R16 passing version) ----------
#define QST 200
#define VST 136
#define PST 72
#define SH_Q  0
#define SH_K0 (SH_Q + 128 * QST)
#define SH_K1 (SH_K0 + 64 * QST)
#define SH_V0 (SH_K1 + 64 * QST)
#define SH_V1 (SH_V0 + 64 * VST)
#define SH_P  (SH_V1 + 64 * VST)
#define ATTN_SMEM_BYTES ((SH_P + 128 * PST) * 2)

__device__ __forceinline__ void attn_stage_kv(
    uint32_t kdst, uint32_t vdst,
    const __half* kvp, const __half* krp, int tid)
{
    #pragma unroll
    for (int i = 0; i < 6; i++) {
        int idx = tid + (i << 8);
        int r = idx / 24, c = idx - r * 24;
        const __half* src = (c < 16)
            ? kvp + (size_t)r * (NH * 256) + (c << 3)
            : krp + (size_t)r * DR + ((c - 16) << 3);
        cp16u(kdst + ((uint32_t)r * QST + (c << 3)) * 2, src);
    }
    #pragma unroll
    for (int i = 0; i < 4; i++) {
        int idx = tid + (i << 8);
        int r = idx >> 4, c = idx & 15;
        cp16u(vdst + ((uint32_t)r * VST + (c << 3)) * 2,
              kvp + (size_t)r * (NH * 256) + DN + (c << 3));
    }
}

__global__ __launch_bounds__(256) void attn_f16(
    const __half* __restrict__ q, const __half* __restrict__ kv,
    const __half* __restrict__ kr, __half* __restrict__ ao)
{
    extern __shared__ __half sh[];
    __half* Qs = sh + SH_Q;
    __half* Ps = sh + SH_P;

    const int tid = threadIdx.x;
    const int wid = tid >> 5, lane = tid & 31;
    const int tg = lane & 3, gp = lane >> 2;
    const int r0 = wid << 4;
    const int bh = blockIdx.y;
    const int b = bh >> 4, h = bh & 15;
    const int q0 = blockIdx.x << 7;
    const size_t tokbase = (size_t)b * S_LEN;
    const float scale = rsqrtf((float)DQK);

    const int lmr = lane & 15;
    const int lmk = (lane >> 4) << 3;
    const uint32_t shb = smem_u32(sh);
    const uint32_t kbuf[2] = {shb + SH_K0 * 2u, shb + SH_K1 * 2u};
    const uint32_t vbuf[2] = {shb + SH_V0 * 2u, shb + SH_V1 * 2u};
    const uint32_t qa_off = shb + ((uint32_t)(r0 + lmr) * QST + lmk) * 2;
    const uint32_t pa_off = shb + SH_P * 2u + ((uint32_t)(r0 + lmr) * PST + lmk) * 2;
    const uint32_t klane = ((uint32_t)lmr * QST + lmk) * 2;
    const uint32_t vlane = ((uint32_t)lmr * VST + lmk) * 2;

    const __half* kvbase = kv + (tokbase) * (NH * 256) + h * 256;
    const __half* krbase = kr + (tokbase) * DR;

    for (int f = tid; f < 128 * 24; f += 256) {
        int r = f / 24, c = (f % 24) << 3;
        *reinterpret_cast<float4*>(&Qs[r * QST + c]) =
            *reinterpret_cast<const float4*>(
                &q[(tokbase + q0 + r) * (NH * DQK) + h * DQK + c]);
    }
    attn_stage_kv(kbuf[0], vbuf[0], kvbase, krbase, tid);
    cp_commit();

    float m_[2] = {-1e30f, -1e30f};
    float l_[2] = {0.f, 0.f};
    float o[16][4];
    #pragma unroll
    for (int nt = 0; nt < 16; nt++)
        #pragma unroll
        for (int r = 0; r < 4; r++) o[nt][r] = 0.f;

    const int NB = S_LEN / 64;
    for (int kbi = 0; kbi < NB; kbi++) {
        const int bsel = kbi & 1;
        __syncthreads();
        if (kbi + 1 < NB) {
            attn_stage_kv(kbuf[bsel ^ 1], vbuf[bsel ^ 1],
                          kvbase + (size_t)(kbi + 1) * 64 * (NH * 256),
                          krbase + (size_t)(kbi + 1) * 64 * DR, tid);
            cp_commit();
            cp_wait1();
        } else {
            cp_wait0();
        }
        __syncthreads();

        const uint32_t ka = kbuf[bsel] + klane;
        const uint32_t va = vbuf[bsel] + vlane;

        float s[8][4];
        #pragma unroll
        for (int nt = 0; nt < 8; nt++)
            #pragma unroll
            for (int r = 0; r < 4; r++) s[nt][r] = 0.f;

        #pragma unroll
        for (int ks = 0; ks < 12; ks++) {
            const uint32_t kby = (uint32_t)(ks << 5);
            uint32_t af[4];
            ldmx4(af, qa_off + kby);
            #pragma unroll
            for (int ntp = 0; ntp < 4; ntp++) {
                uint32_t bf[4];
                ldmx4(bf, ka + (uint32_t)(ntp << 4) * QST * 2 + kby);
                mma_f16(s[2 * ntp],     af[0], af[1], af[2], af[3], bf[0], bf[2]);
                mma_f16(s[2 * ntp + 1], af[0], af[1], af[2], af[3], bf[1], bf[3]);
            }
        }

        #pragma unroll
        for (int hr = 0; hr < 2; hr++) {
            float mx = -1e30f;
            #pragma unroll
            for (int nt = 0; nt < 8; nt++) {
                s[nt][2 * hr]     *= scale;
                s[nt][2 * hr + 1] *= scale;
                mx = fmaxf(mx, fmaxf(s[nt][2 * hr], s[nt][2 * hr + 1]));
            }
            mx = fmaxf(mx, __shfl_xor_sync(~0u, mx, 1));
            mx = fmaxf(mx, __shfl_xor_sync(~0u, mx, 2));
            float nm = fmaxf(m_[hr], mx);
            float alpha = __expf(m_[hr] - nm);
            float ls = 0.f;
            #pragma unroll
            for (int nt = 0; nt < 8; nt++) {
                float p0 = __expf(s[nt][2 * hr] - nm);
                float p1 = __expf(s[nt][2 * hr + 1] - nm);
                s[nt][2 * hr] = p0; s[nt][2 * hr + 1] = p1;
                ls += p0 + p1;
            }
            ls += __shfl_xor_sync(~0u, ls, 1);
            ls += __shfl_xor_sync(~0u, ls, 2);
            l_[hr] = l_[hr] * alpha + ls;
            m_[hr] = nm;
            #pragma unroll
            for (int nt = 0; nt < 16; nt++) {
                o[nt][2 * hr]     *= alpha;
                o[nt][2 * hr + 1] *= alpha;
            }
            int pr = r0 + gp + (hr << 3);
            #pragma unroll
            for (int nt = 0; nt < 8; nt++)
                sth2(&Ps[pr * PST + (nt << 3) + (tg << 1)],
                     pkh2(s[nt][2 * hr], s[nt][2 * hr + 1]));
        }
        __syncwarp();

        #pragma unroll
        for (int ks = 0; ks < 4; ks++) {
            const uint32_t kof = (uint32_t)(ks << 4) * VST * 2;
            uint32_t af[4];
            ldmx4(af, pa_off + (uint32_t)(ks << 5));
            #pragma unroll
            for (int ntp = 0; ntp < 8; ntp++) {
                uint32_t bf[4];
                ldmx4t(bf, va + kof + (uint32_t)(ntp << 4) * 2);
                mma_f16(o[2 * ntp],     af[0], af[1], af[2], af[3], bf[0], bf[1]);
                mma_f16(o[2 * ntp + 1], af[0], af[1], af[2], af[3], bf[2], bf[3]);
            }
        }
    }

    float inv0 = 1.0f / l_[0], inv1 = 1.0f / l_[1];
    size_t rlo = (tokbase + q0 + r0 + gp) * (size_t)(NH * DVV) + h * DVV;
    size_t rhi = (tokbase + q0 + r0 + gp + 8) * (size_t)(NH * DVV) + h * DVV;
    #pragma unroll
    for (int nt = 0; nt < 16; nt++) {
        int col = (nt << 3) + (tg << 1);
        sth2(&ao[rlo + col], pkh2(o[nt][0] * inv0, o[nt][1] * inv0));
        sth2(&ao[rhi + col], pkh2(o[nt][2] * inv1, o[nt][3] * inv1));
    }
}

// ---------------- launch --------------------------------------------------------
extern "C" void kernel_launch(void* const* d_in, const int* in_sizes, int n_in,
                              void* d_out, int out_size)
{
    const float* hidden  = (const float*)d_in[0];
    const float* cosb    = (const float*)d_in[1];
    const float* sinb    = (const float*)d_in[2];
    const float* q_a_w   = (const float*)d_in[3];
    const float* q_a_ln  = (const float*)d_in[4];
    const float* q_b_w   = (const float*)d_in[5];
    const float* kv_a_w  = (const float*)d_in[6];
    const float* kv_a_ln = (const float*)d_in[7];
    const float* kv_b_w  = (const float*)d_in[8];
    const float* o_w     = (const float*)d_in[9];
    float* out = (float*)d_out;

    __half *qac, *qa, *qq, *ckn, *kvf, *kr, *ao, *hid;
    __half *wabT, *wqbT, *wkvbT, *woT;
    cudaGetSymbolAddress((void**)&qac,   g_qac);
    cudaGetSymbolAddress((void**)&qa,    g_qa);
    cudaGetSymbolAddress((void**)&qq,    g_q);
    cudaGetSymbolAddress((void**)&ckn,   g_ckn);
    cudaGetSymbolAddress((void**)&kvf,   g_kv);
    cudaGetSymbolAddress((void**)&kr,    g_kr);
    cudaGetSymbolAddress((void**)&ao,    g_ao);
    cudaGetSymbolAddress((void**)&hid,   g_hid);
    cudaGetSymbolAddress((void**)&wabT,  g_wabT);
    cudaGetSymbolAddress((void**)&wqbT,  g_wqbT);
    cudaGetSymbolAddress((void**)&wkvbT, g_wkvbT);
    cudaGetSymbolAddress((void**)&woT,   g_woT);

    cudaFuncSetAttribute(attn_f16,
        cudaFuncAttributeMaxDynamicSharedMemorySize, ATTN_SMEM_BYTES);
    cudaFuncSetAttribute(gemm_f16k,
        cudaFuncAttributeMaxDynamicSharedMemorySize, GEMM_SMEM);

    // [0] hidden -> fp16
    round_h<<<(NTOK * HID / 4 + 255) / 256, 256>>>(hidden, hid, NTOK * HID / 4);

    // [1] transpose weights -> fp16 [N][K]; q_a and kv_a stacked into wabT
    TAll ta;
    ta.p[0] = {q_a_w,  wabT,                      HID, QL,       QL};
    ta.p[1] = {kv_a_w, wabT + (size_t)QL * HID,   HID, CKV_W,    640};
    ta.p[2] = {q_b_w,  wqbT,  QL,  NH * DQK, NH * DQK};
    ta.p[3] = {kv_b_w, wkvbT, KVL, NH * 256, NH * 256};
    ta.p[4] = {o_w,    woT,   HID, HID,      HID};
    transpose_h<<<dim3(128, 64, 5), dim3(32, 8)>>>(ta);

    // [2] fused (q_a | ckv) = hid @ wabT : [4096, 2176]
    gemm_f16k<<<dim3(QAC_W / 128, NTOK / 128), 256, GEMM_SMEM>>>(
        hid, wabT, qac, NTOK, QAC_W, HID, 0);
    // [3] rmsnorm q_a slice -> qa
    rmsnorm_h<<<NTOK, 256>>>(qac, q_a_ln, qa, QAC_W, QL, QL);
    // [4] rmsnorm ckv slice -> ckn
    rmsnorm_h<<<NTOK, 256>>>(qac + QL, kv_a_ln, ckn, QAC_W, KVL, KVL);
    // [5] q = qa @ q_b_w
    gemm_f16k<<<dim3(NH * DQK / 128, NTOK / 128), 256, GEMM_SMEM>>>(qa, wqbT, qq, NTOK, NH * DQK, QL, 0);
    // [6] kv = ckn @ kv_b_w
    gemm_f16k<<<dim3(NH * 256 / 128, NTOK / 128), 256, GEMM_SMEM>>>(ckn, wkvbT, kvf, NTOK, NH * 256, KVL, 0);
    // [7] rope q (in place)
    rope_q_h<<<NTOK, NH * 32>>>(qq, cosb, sinb);
    // [8] rope k_rope (from qac) -> kr
    rope_k_h<<<NTOK, 32>>>(qac, cosb, sinb, kr);
    // [9] attention
    attn_f16<<<dim3(S_LEN / 128, BATCH * NH), 256, ATTN_SMEM_BYTES>>>(qq, kvf, kr, ao);
    // [10] out = ao @ o_w (fp32 out)
    gemm_f16k<<<dim3(HID / 128, NTOK / 128), 256, GEMM_SMEM>>>(ao, woT, out, NTOK, HID, HID, 1);
}